// round 14
// baseline (speedup 1.0000x reference)
#include <cuda_runtime.h>
#include <cuda_bf16.h>
#include <cstdint>
#include <math.h>

#define H_    12
#define D_    128
#define NX    2048
#define NY    256
#define S_    2304
#define DX_   1536
#define DY_   768
#define QKVN  4608

typedef __nv_bfloat16 bf16;

// ---------------- scratch (static device globals; no allocation) ----------------
__device__ __align__(256) float g_qkvx[(size_t)NX * QKVN];
__device__ __align__(256) float g_qkvy[(size_t)NY * QKVN];
__device__ __align__(256) bf16 g_xm_h[(size_t)NX * DX_],  g_xm_l[(size_t)NX * DX_];
__device__ __align__(256) bf16 g_ym_h[(size_t)NY * DY_],  g_ym_l[(size_t)NY * DY_];
__device__ __align__(256) bf16 g_WqxT_h[(size_t)QKVN * DX_], g_WqxT_l[(size_t)QKVN * DX_];
__device__ __align__(256) bf16 g_WqyT_h[(size_t)QKVN * DY_], g_WqyT_l[(size_t)QKVN * DY_];
__device__ __align__(256) bf16 g_WpxT_h[(size_t)DX_ * DX_],  g_WpxT_l[(size_t)DX_ * DX_];
__device__ __align__(256) bf16 g_WpyT_h[(size_t)DY_ * DX_],  g_WpyT_l[(size_t)DY_ * DX_];
__device__ __align__(256) bf16 g_Qh[(size_t)H_ * S_ * D_], g_Ql[(size_t)H_ * S_ * D_];
__device__ __align__(256) bf16 g_Kh[(size_t)H_ * S_ * D_], g_Kl[(size_t)H_ * S_ * D_];
__device__ __align__(256) bf16 g_Vth[(size_t)H_ * D_ * S_], g_Vtl[(size_t)H_ * D_ * S_];
__device__ __align__(256) bf16 g_Oh[(size_t)S_ * DX_],      g_Ol[(size_t)S_ * DX_];

// ---------------- small helpers ----------------
__device__ __forceinline__ float warp_sum(float v) {
    #pragma unroll
    for (int o = 16; o; o >>= 1) v += __shfl_xor_sync(0xffffffffu, v, o);
    return v;
}
__device__ float block_red(float v, float* sbuf, bool ismax) {
    #pragma unroll
    for (int o = 16; o; o >>= 1)
        v = ismax ? fmaxf(v, __shfl_xor_sync(0xffffffffu, v, o))
                  : v + __shfl_xor_sync(0xffffffffu, v, o);
    int w = threadIdx.x >> 5, nw = blockDim.x >> 5;
    if ((threadIdx.x & 31) == 0) sbuf[w] = v;
    __syncthreads();
    if (threadIdx.x < 32) {
        float t = (threadIdx.x < nw) ? sbuf[threadIdx.x] : (ismax ? -1e30f : 0.f);
        #pragma unroll
        for (int o = 16; o; o >>= 1)
            t = ismax ? fmaxf(t, __shfl_xor_sync(0xffffffffu, t, o))
                      : t + __shfl_xor_sync(0xffffffffu, t, o);
        if (threadIdx.x == 0) sbuf[0] = t;
    }
    __syncthreads();
    float r = sbuf[0];
    __syncthreads();
    return r;
}
__device__ __forceinline__ void split_bf16(float v, bf16& h, bf16& l) {
    h = __float2bfloat16(v);
    l = __float2bfloat16(v - __bfloat162float(h));
}
__device__ __forceinline__ uint32_t pack_hi2(float a, float b, uint32_t& lo) {
    bf16 h0, l0, h1, l1;
    split_bf16(a, h0, l0); split_bf16(b, h1, l1);
    __nv_bfloat162 hp(h0, h1), lp(l0, l1);
    lo = *(uint32_t*)&lp;
    return *(uint32_t*)&hp;
}
__device__ __forceinline__ void store4_split(bf16* dh, bf16* dl,
                                             float v0, float v1, float v2, float v3) {
    uint32_t l0, l1;
    uint32_t h0 = pack_hi2(v0, v1, l0);
    uint32_t h1 = pack_hi2(v2, v3, l1);
    *(uint2*)dh = make_uint2(h0, h1);
    *(uint2*)dl = make_uint2(l0, l1);
}
__device__ __forceinline__ uint32_t smem_u32(const void* p) {
    return (uint32_t)__cvta_generic_to_shared(p);
}
__device__ __forceinline__ void cp16(uint32_t s, const void* g) {
    asm volatile("cp.async.cg.shared.global [%0], [%1], 16;" :: "r"(s), "l"(g));
}
__device__ __forceinline__ void ldmx4(uint32_t* r, uint32_t a) {
    asm volatile("ldmatrix.sync.aligned.m8n8.x4.shared.b16 {%0,%1,%2,%3}, [%4];"
                 : "=r"(r[0]), "=r"(r[1]), "=r"(r[2]), "=r"(r[3]) : "r"(a));
}
__device__ __forceinline__ void mma16816(float* c, const uint32_t* a, uint32_t b0, uint32_t b1) {
    asm volatile(
        "mma.sync.aligned.m16n8k16.row.col.f32.bf16.bf16.f32 "
        "{%0,%1,%2,%3}, {%4,%5,%6,%7}, {%8,%9}, {%0,%1,%2,%3};"
        : "+f"(c[0]), "+f"(c[1]), "+f"(c[2]), "+f"(c[3])
        : "r"(a[0]), "r"(a[1]), "r"(a[2]), "r"(a[3]), "r"(b0), "r"(b1));
}

// ---------------- bf16x3 HMMA GEMM, narrow 128x128 ----------------
#define PADB   80
#define TILEB  (128 * PADB)
#define STAGEB (4 * TILEB)
#define GSMEM  (2 * STAGEB)

__global__ __launch_bounds__(256, 2)
void mma_gemm(const bf16* __restrict__ Ah, const bf16* __restrict__ Al,
              const bf16* __restrict__ Bh, const bf16* __restrict__ Bl,
              const float* __restrict__ bias,
              float* __restrict__ Cf, bf16* __restrict__ Ch, bf16* __restrict__ Cl,
              int K, int lda, int ldb, int ldc,
              long sA, long sB, long sC)
{
    extern __shared__ char smem[];
    uint32_t sb = smem_u32(smem);
    int tid = threadIdx.x, wid = tid >> 5, lane = tid & 31;
    int wr = wid >> 1, wc = wid & 1;

    const bf16* pAh = Ah + (size_t)blockIdx.z * sA + (size_t)blockIdx.y * 128 * lda;
    const bf16* pAl = Al + (size_t)blockIdx.z * sA + (size_t)blockIdx.y * 128 * lda;
    const bf16* pBh = Bh + (size_t)blockIdx.z * sB + (size_t)blockIdx.x * 128 * ldb;
    const bf16* pBl = Bl + (size_t)blockIdx.z * sB + (size_t)blockIdx.x * 128 * ldb;

    const int NC = K >> 5;

    auto load_stage = [&](int st, int k0) {
        uint32_t s0 = sb + st * STAGEB;
        const bf16* srcs[4] = {pAh, pAl, pBh, pBl};
        #pragma unroll
        for (int t = 0; t < 4; t++) {
            int ldt = (t < 2) ? lda : ldb;
            const char* gb = (const char*)srcs[t] + (size_t)k0 * 2;
            #pragma unroll
            for (int i = 0; i < 2; i++) {
                int idx = tid + (i << 8);
                int row = idx >> 2, ch = idx & 3;
                cp16(s0 + t * TILEB + row * PADB + ch * 16,
                     gb + (size_t)row * ldt * 2 + ch * 16);
            }
        }
        asm volatile("cp.async.commit_group;");
    };

    float acc[2][8][4];
    #pragma unroll
    for (int i = 0; i < 2; i++)
        #pragma unroll
        for (int j = 0; j < 8; j++)
            #pragma unroll
            for (int r = 0; r < 4; r++) acc[i][j][r] = 0.f;

    int r8 = lane & 7, seg = lane >> 3;
    int a_row = (seg & 1) * 8 + r8;
    int a_kb  = (seg >> 1) * 16;
    int b_row = (seg >> 1) * 8 + r8;
    int b_kb  = (seg & 1) * 16;

    load_stage(0, 0);

    for (int i = 0; i < NC; i++) {
        asm volatile("cp.async.wait_group 0;");
        __syncthreads();
        if (i + 1 < NC) load_stage((i + 1) & 1, (i + 1) << 5);

        uint32_t base = sb + (i & 1) * STAGEB;
        #pragma unroll
        for (int ks = 0; ks < 2; ks++) {
            int kb = ks * 32;
            uint32_t ah[2][4], al[2][4], bh[4][4], bl[4][4];
            #pragma unroll
            for (int mi = 0; mi < 2; mi++) {
                uint32_t ad = base + (wr * 32 + mi * 16 + a_row) * PADB + kb + a_kb;
                ldmx4(ah[mi], ad);
                ldmx4(al[mi], ad + TILEB);
            }
            #pragma unroll
            for (int nj = 0; nj < 4; nj++) {
                uint32_t bd = base + 2 * TILEB + (wc * 64 + nj * 16 + b_row) * PADB + kb + b_kb;
                ldmx4(bh[nj], bd);
                ldmx4(bl[nj], bd + TILEB);
            }
            #pragma unroll
            for (int mi = 0; mi < 2; mi++)
                #pragma unroll
                for (int nt = 0; nt < 8; nt++) {
                    int nj = nt >> 1, hf = (nt & 1) * 2;
                    mma16816(acc[mi][nt], ah[mi], bh[nj][hf], bh[nj][hf + 1]);
                    mma16816(acc[mi][nt], ah[mi], bl[nj][hf], bl[nj][hf + 1]);
                    mma16816(acc[mi][nt], al[mi], bh[nj][hf], bh[nj][hf + 1]);
                }
        }
    }

    int brow = blockIdx.y * 128 + wr * 32 + (lane >> 2);
    int bcol = blockIdx.x * 128 + wc * 64 + (lane & 3) * 2;
    #pragma unroll
    for (int mi = 0; mi < 2; mi++)
        #pragma unroll
        for (int nt = 0; nt < 8; nt++)
            #pragma unroll
            for (int rh = 0; rh < 2; rh++) {
                int rr = brow + mi * 16 + rh * 8;
                int cc = bcol + nt * 8;
                float v0 = acc[mi][nt][rh * 2 + 0];
                float v1 = acc[mi][nt][rh * 2 + 1];
                if (bias) { v0 += __ldg(bias + cc); v1 += __ldg(bias + cc + 1); }
                size_t ci = (size_t)blockIdx.z * sC + (size_t)rr * ldc + cc;
                if (Cf) *(float2*)(Cf + ci) = make_float2(v0, v1);
                if (Ch) {
                    bf16 h0, l0, h1, l1;
                    split_bf16(v0, h0, l0); split_bf16(v1, h1, l1);
                    *(__nv_bfloat162*)(Ch + ci) = __nv_bfloat162(h0, h1);
                    *(__nv_bfloat162*)(Cl + ci) = __nv_bfloat162(l0, l1);
                }
            }
}

// ---------------- bf16x3 HMMA GEMM, wide 128x256 ----------------
#define WPAD  80
#define WTA   (128 * WPAD)
#define WTB   (256 * WPAD)
#define WSTG  (2 * WTA + 2 * WTB)
#define WSMEM (3 * WSTG)

__global__ __launch_bounds__(256, 1)
void mma_gemm_wide(const bf16* __restrict__ Ah, const bf16* __restrict__ Al,
                   const bf16* __restrict__ Bh, const bf16* __restrict__ Bl,
                   const float* __restrict__ bias, float* __restrict__ Cf,
                   int K, int lda, int ldb, int ldc)
{
    extern __shared__ char smem[];
    uint32_t sb = smem_u32(smem);
    int tid = threadIdx.x, wid = tid >> 5, lane = tid & 31;
    int wr = wid & 1, wc = wid >> 1;

    const bf16* pAh = Ah + (size_t)blockIdx.y * 128 * lda;
    const bf16* pAl = Al + (size_t)blockIdx.y * 128 * lda;
    const bf16* pBh = Bh + (size_t)blockIdx.x * 256 * ldb;
    const bf16* pBl = Bl + (size_t)blockIdx.x * 256 * ldb;

    const int NC = K >> 5;

    auto load_stage = [&](int st, int k0) {
        uint32_t s0 = sb + st * WSTG;
        const char* gah = (const char*)pAh + (size_t)k0 * 2;
        const char* gal = (const char*)pAl + (size_t)k0 * 2;
        #pragma unroll
        for (int i = 0; i < 2; i++) {
            int idx = tid + (i << 8);
            int row = idx >> 2, ch = idx & 3;
            size_t go = (size_t)row * lda * 2 + ch * 16;
            cp16(s0 + row * WPAD + ch * 16,        gah + go);
            cp16(s0 + WTA + row * WPAD + ch * 16,  gal + go);
        }
        const char* gbh = (const char*)pBh + (size_t)k0 * 2;
        const char* gbl = (const char*)pBl + (size_t)k0 * 2;
        #pragma unroll
        for (int i = 0; i < 4; i++) {
            int idx = tid + (i << 8);
            int row = idx >> 2, ch = idx & 3;
            size_t go = (size_t)row * ldb * 2 + ch * 16;
            cp16(s0 + 2 * WTA + row * WPAD + ch * 16,       gbh + go);
            cp16(s0 + 2 * WTA + WTB + row * WPAD + ch * 16, gbl + go);
        }
        asm volatile("cp.async.commit_group;");
    };

    float acc[4][8][4];
    #pragma unroll
    for (int i = 0; i < 4; i++)
        #pragma unroll
        for (int j = 0; j < 8; j++)
            #pragma unroll
            for (int r = 0; r < 4; r++) acc[i][j][r] = 0.f;

    int r8 = lane & 7, seg = lane >> 3;
    int a_row = (seg & 1) * 8 + r8;
    int a_kb  = (seg >> 1) * 16;
    int b_row = (seg >> 1) * 8 + r8;
    int b_kb  = (seg & 1) * 16;

    load_stage(0, 0);
    load_stage(1, 32);

    for (int i = 0; i < NC; i++) {
        if (i < NC - 1) { asm volatile("cp.async.wait_group 1;"); }
        else            { asm volatile("cp.async.wait_group 0;"); }
        __syncthreads();
        if (i + 2 < NC) load_stage((i + 2) % 3, (i + 2) << 5);

        uint32_t base = sb + (i % 3) * WSTG;
        #pragma unroll
        for (int ks = 0; ks < 2; ks++) {
            int kb = ks * 32;
            uint32_t ah[4][4], al[4][4];
            #pragma unroll
            for (int mi = 0; mi < 4; mi++) {
                uint32_t ad = base + (wr * 64 + mi * 16 + a_row) * WPAD + kb + a_kb;
                ldmx4(ah[mi], ad);
                ldmx4(al[mi], ad + WTA);
            }
            #pragma unroll
            for (int nj = 0; nj < 4; nj++) {
                uint32_t bh[4], bl[4];
                uint32_t bd = base + 2 * WTA + (wc * 64 + nj * 16 + b_row) * WPAD + kb + b_kb;
                ldmx4(bh, bd);
                ldmx4(bl, bd + WTB);
                #pragma unroll
                for (int mi = 0; mi < 4; mi++)
                    #pragma unroll
                    for (int half = 0; half < 2; half++) {
                        int nt = nj * 2 + half, hf = half * 2;
                        mma16816(acc[mi][nt], ah[mi], bh[hf], bh[hf + 1]);
                        mma16816(acc[mi][nt], ah[mi], bl[hf], bl[hf + 1]);
                        mma16816(acc[mi][nt], al[mi], bh[hf], bh[hf + 1]);
                    }
            }
        }
    }

    int brow = blockIdx.y * 128 + wr * 64 + (lane >> 2);
    int bcol = blockIdx.x * 256 + wc * 64 + (lane & 3) * 2;
    #pragma unroll
    for (int mi = 0; mi < 4; mi++)
        #pragma unroll
        for (int nt = 0; nt < 8; nt++)
            #pragma unroll
            for (int rh = 0; rh < 2; rh++) {
                int rr = brow + mi * 16 + rh * 8;
                int cc = bcol + nt * 8;
                float v0 = acc[mi][nt][rh * 2 + 0];
                float v1 = acc[mi][nt][rh * 2 + 1];
                if (bias) { v0 += __ldg(bias + cc); v1 += __ldg(bias + cc + 1); }
                *(float2*)(Cf + (size_t)rr * ldc + cc) = make_float2(v0, v1);
            }
}

// ---------------- fused flash attention (pipelined waits: wait-before-use) ----------------
#define QPAD  272
#define KPAD  272
#define VPAD  144
#define QTB   (64 * QPAD)
#define KTB   (64 * KPAD)
#define VTB   (128 * VPAD)
#define STGB  (2 * KTB + 2 * VTB)
#define FSMEM (2 * QTB + 2 * STGB)

__global__ __launch_bounds__(256, 1)
void flash_attn(const bf16* __restrict__ Qh_, const bf16* __restrict__ Ql_,
                const bf16* __restrict__ Kh_, const bf16* __restrict__ Kl_,
                const bf16* __restrict__ Vh_, const bf16* __restrict__ Vl_,
                bf16* __restrict__ Oh_, bf16* __restrict__ Ol_)
{
    extern __shared__ char smem[];
    uint32_t sb = smem_u32(smem);
    int tid = threadIdx.x, wid = tid >> 5, lane = tid & 31;
    int wg = wid >> 2, wid4 = wid & 3, tid4 = tid & 127;
    int h = blockIdx.y;
    int q0 = blockIdx.x * 64;

    const bf16* Qhb = Qh_ + ((size_t)h * S_ + q0) * D_;
    const bf16* Qlb = Ql_ + ((size_t)h * S_ + q0) * D_;
    const bf16* Khb = Kh_ + (size_t)h * S_ * D_;
    const bf16* Klb = Kl_ + (size_t)h * S_ * D_;
    const bf16* Vhb = Vh_ + (size_t)h * D_ * S_;
    const bf16* Vlb = Vl_ + (size_t)h * D_ * S_;

    const uint32_t Qs = sb, STG0 = sb + 2 * QTB;
    const uint32_t MYB = STG0 + (uint32_t)wg * STGB;

    // Q load (block-wide; bundled into the K(0) commit group)
    #pragma unroll
    for (int i = 0; i < 4; i++) {
        int c = tid + (i << 8);
        int row = c >> 4, ch = c & 15;
        cp16(Qs + row * QPAD + ch * 16,        (const char*)Qhb + (size_t)row * 256 + ch * 16);
        cp16(Qs + QTB + row * QPAD + ch * 16,  (const char*)Qlb + (size_t)row * 256 + ch * 16);
    }
    auto load_K = [&](int blk) {
        const char* kh = (const char*)(Khb + (size_t)blk * 64 * D_);
        const char* kl = (const char*)(Klb + (size_t)blk * 64 * D_);
        #pragma unroll
        for (int i = 0; i < 8; i++) {
            int c = tid4 + (i << 7);
            int row = c >> 4, ch = c & 15;
            cp16(MYB + row * KPAD + ch * 16,       kh + (size_t)row * 256 + ch * 16);
            cp16(MYB + KTB + row * KPAD + ch * 16, kl + (size_t)row * 256 + ch * 16);
        }
        asm volatile("cp.async.commit_group;");
    };
    auto load_V = [&](int blk) {
        const char* vh = (const char*)(Vhb + (size_t)blk * 64);
        const char* vl = (const char*)(Vlb + (size_t)blk * 64);
        #pragma unroll
        for (int i = 0; i < 8; i++) {
            int c = tid4 + (i << 7);
            int row = c >> 3, ch = c & 7;
            cp16(MYB + 2 * KTB + row * VPAD + ch * 16,       vh + (size_t)row * S_ * 2 + ch * 16);
            cp16(MYB + 2 * KTB + VTB + row * VPAD + ch * 16, vl + (size_t)row * S_ * 2 + ch * 16);
        }
        asm volatile("cp.async.commit_group;");
    };
    // group sequence per thread: [Q+K(0)], [V(0)], [K(1)], [V(1)], ...
    load_K(wg);
    load_V(wg);
    // ensure Q (+K0) landed, then block-wide visibility of Q for all warps
    asm volatile("cp.async.wait_group 1;");
    __syncthreads();

    int r8 = lane & 7, seg = lane >> 3;
    int a_row = (seg & 1) * 8 + r8;
    int a_kb  = (seg >> 1) * 16;
    int b_row = (seg >> 1) * 8 + r8;
    int b_kb  = (seg & 1) * 16;

    float o[16][4];
    #pragma unroll
    for (int t = 0; t < 16; t++)
        #pragma unroll
        for (int r = 0; r < 4; r++) o[t][r] = 0.f;
    float m0 = -1e30f, m1 = -1e30f, l0 = 0.f, l1 = 0.f;
    const float sc = 0.08838834764831845f;
    const int bar_id = 1 + wg;

    const int NIT = (S_ / 64) / 2;
    for (int it = 0; it < NIT; it++) {
        uint32_t Ks = MYB;
        uint32_t Vs = MYB + 2 * KTB;
        bool more = (it + 1 < NIT);

        // ---- need K(it): outstanding = {K(it), V(it)} -> allow 1 pending ----
        asm volatile("cp.async.wait_group 1;");
        asm volatile("bar.sync %0, 128;" :: "r"(bar_id) : "memory");

        float st[8][4];
        #pragma unroll
        for (int t = 0; t < 8; t++)
            #pragma unroll
            for (int r = 0; r < 4; r++) st[t][r] = 0.f;

        #pragma unroll
        for (int ks = 0; ks < 8; ks++) {
            int kb = ks * 32;
            uint32_t qh[4], ql[4], kh[4][4], kl[4][4];
            uint32_t qa = Qs + (wid4 * 16 + a_row) * QPAD + kb + a_kb;
            ldmx4(qh, qa);
            ldmx4(ql, qa + QTB);
            #pragma unroll
            for (int nj = 0; nj < 4; nj++) {
                uint32_t ka = Ks + (nj * 16 + b_row) * KPAD + kb + b_kb;
                ldmx4(kh[nj], ka);
                ldmx4(kl[nj], ka + KTB);
            }
            #pragma unroll
            for (int nt = 0; nt < 8; nt++) {
                int nj = nt >> 1, hf = (nt & 1) * 2;
                mma16816(st[nt], qh, kh[nj][hf], kh[nj][hf + 1]);
                mma16816(st[nt], qh, kl[nj][hf], kl[nj][hf + 1]);
                mma16816(st[nt], ql, kh[nj][hf], kh[nj][hf + 1]);
            }
        }

        // K buffer consumed by all warps of this wg -> refill (no wait here)
        asm volatile("bar.sync %0, 128;" :: "r"(bar_id) : "memory");
        if (more) load_K(wg + 2 * (it + 1));

        // ---- online softmax (overlaps K(it+1) flight) ----
        float bm0 = -1e30f, bm1 = -1e30f;
        #pragma unroll
        for (int t = 0; t < 8; t++) {
            bm0 = fmaxf(bm0, fmaxf(st[t][0], st[t][1]));
            bm1 = fmaxf(bm1, fmaxf(st[t][2], st[t][3]));
        }
        #pragma unroll
        for (int off = 1; off <= 2; off <<= 1) {
            bm0 = fmaxf(bm0, __shfl_xor_sync(0xffffffffu, bm0, off));
            bm1 = fmaxf(bm1, __shfl_xor_sync(0xffffffffu, bm1, off));
        }
        float nm0 = fmaxf(m0, bm0), nm1 = fmaxf(m1, bm1);
        float al0 = __expf((m0 - nm0) * sc), al1 = __expf((m1 - nm1) * sc);
        float ps0 = 0.f, ps1 = 0.f;
        #pragma unroll
        for (int t = 0; t < 8; t++) {
            st[t][0] = __expf((st[t][0] - nm0) * sc);
            st[t][1] = __expf((st[t][1] - nm0) * sc);
            st[t][2] = __expf((st[t][2] - nm1) * sc);
            st[t][3] = __expf((st[t][3] - nm1) * sc);
            ps0 += st[t][0] + st[t][1];
            ps1 += st[t][2] + st[t][3];
        }
        #pragma unroll
        for (int off = 1; off <= 2; off <<= 1) {
            ps0 += __shfl_xor_sync(0xffffffffu, ps0, off);
            ps1 += __shfl_xor_sync(0xffffffffu, ps1, off);
        }
        l0 = l0 * al0 + ps0;
        l1 = l1 * al1 + ps1;
        m0 = nm0; m1 = nm1;
        #pragma unroll
        for (int t = 0; t < 16; t++) {
            o[t][0] *= al0; o[t][1] *= al0;
            o[t][2] *= al1; o[t][3] *= al1;
        }

        // ---- need V(it): outstanding = {V(it), K(it+1)?} ----
        if (more) { asm volatile("cp.async.wait_group 1;"); }
        else      { asm volatile("cp.async.wait_group 0;"); }
        asm volatile("bar.sync %0, 128;" :: "r"(bar_id) : "memory");

        #pragma unroll
        for (int g = 0; g < 4; g++) {
            uint32_t aph[4], apl[4];
            #pragma unroll
            for (int half = 0; half < 2; half++) {
                float* s0 = st[2 * g + half];
                aph[2 * half + 0] = pack_hi2(s0[0], s0[1], apl[2 * half + 0]);
                aph[2 * half + 1] = pack_hi2(s0[2], s0[3], apl[2 * half + 1]);
            }
            #pragma unroll
            for (int nj = 0; nj < 8; nj++) {
                uint32_t vh[4], vl[4];
                uint32_t va = Vs + (nj * 16 + b_row) * VPAD + g * 32 + b_kb;
                ldmx4(vh, va);
                ldmx4(vl, va + VTB);
                #pragma unroll
                for (int half = 0; half < 2; half++) {
                    int t = nj * 2 + half;
                    int hf = half * 2;
                    mma16816(o[t], aph, vh[hf], vh[hf + 1]);
                    mma16816(o[t], apl, vh[hf], vh[hf + 1]);
                    mma16816(o[t], aph, vl[hf], vl[hf + 1]);
                }
            }
        }

        // V buffer consumed -> refill (no wait; next iter waits before use)
        asm volatile("bar.sync %0, 128;" :: "r"(bar_id) : "memory");
        if (more) load_V(wg + 2 * (it + 1));
    }

    float* sf = (float*)smem;
    __syncthreads();
    if (wg == 1) {
        float* dml = sf + tid4 * 4;
        dml[0] = m0; dml[1] = m1; dml[2] = l0; dml[3] = l1;
        float* doo = sf + 512 + tid4 * 64;
        #pragma unroll
        for (int t = 0; t < 16; t++)
            *(float4*)(doo + t * 4) = make_float4(o[t][0], o[t][1], o[t][2], o[t][3]);
    }
    __syncthreads();
    if (wg == 0) {
        float* pml = sf + tid4 * 4;
        float pm0 = pml[0], pm1 = pml[1], pl0 = pml[2], pl1 = pml[3];
        float* poo = sf + 512 + tid4 * 64;
        float M0 = fmaxf(m0, pm0), M1 = fmaxf(m1, pm1);
        float w00 = __expf((m0 - M0) * sc), w01 = __expf((pm0 - M0) * sc);
        float w10 = __expf((m1 - M1) * sc), w11 = __expf((pm1 - M1) * sc);
        float L0 = l0 * w00 + pl0 * w01;
        float L1 = l1 * w10 + pl1 * w11;
        float i0 = 1.f / L0, i1 = 1.f / L1;
        int sr0 = q0 + wid4 * 16 + (lane >> 2);
        #pragma unroll
        for (int t = 0; t < 16; t++) {
            float4 po = *(float4*)(poo + t * 4);
            float v0 = (o[t][0] * w00 + po.x * w01) * i0;
            float v1 = (o[t][1] * w00 + po.y * w01) * i0;
            float v2 = (o[t][2] * w10 + po.z * w11) * i1;
            float v3 = (o[t][3] * w10 + po.w * w11) * i1;
            int cc = h * 128 + t * 8 + (lane & 3) * 2;
            bf16 h0, lo0, h1, lo1;
            split_bf16(v0, h0, lo0); split_bf16(v1, h1, lo1);
            size_t ci = (size_t)sr0 * DX_ + cc;
            *(__nv_bfloat162*)(Oh_ + ci) = __nv_bfloat162(h0, h1);
            *(__nv_bfloat162*)(Ol_ + ci) = __nv_bfloat162(lo0, lo1);
            split_bf16(v2, h0, lo0); split_bf16(v3, h1, lo1);
            ci = (size_t)(sr0 + 8) * DX_ + cc;
            *(__nv_bfloat162*)(Oh_ + ci) = __nv_bfloat162(h0, h1);
            *(__nv_bfloat162*)(Ol_ + ci) = __nv_bfloat162(lo0, lo1);
        }
    }
}

// ---------------- RMSNorm + modulation, split hi/lo ----------------
__global__ void rms_mod_split(const float* __restrict__ X, const float* __restrict__ sc,
                              bf16* __restrict__ oh, bf16* __restrict__ ol, int Dm, float eps) {
    __shared__ float sbuf[32];
    size_t row = blockIdx.x;
    const float* xr = X + row * Dm;
    float ss = 0.f;
    for (int i = threadIdx.x; i < Dm; i += blockDim.x) { float t = xr[i]; ss += t * t; }
    ss = block_red(ss, sbuf, false);
    float r = rsqrtf(ss / (float)Dm + eps);
    for (int i = threadIdx.x; i < Dm; i += blockDim.x) {
        float v = xr[i] * r * (1.f + sc[i]);
        bf16 h, l; split_bf16(v, h, l);
        oh[row * Dm + i] = h; ol[row * Dm + i] = l;
    }
}

// ---------------- dual weight transpose + split ----------------
__global__ void wconv2(const float* __restrict__ W0, bf16* __restrict__ Th0, bf16* __restrict__ Tl0,
                       int K0, int N0,
                       const float* __restrict__ W1, bf16* __restrict__ Th1, bf16* __restrict__ Tl1,
                       int K1, int N1) {
    const float* W; bf16 *Th, *Tl; int K, N;
    if (blockIdx.z == 0) { W = W0; Th = Th0; Tl = Tl0; K = K0; N = N0; }
    else                 { W = W1; Th = Th1; Tl = Tl1; K = K1; N = N1; }
    int n0 = blockIdx.x * 32, k0 = blockIdx.y * 32;
    if (n0 >= N || k0 >= K) return;
    __shared__ float t[32][33];
    int tx = threadIdx.x, ty = threadIdx.y;
    #pragma unroll
    for (int j = 0; j < 32; j += 8)
        t[ty + j][tx] = W[(size_t)(k0 + ty + j) * N + n0 + tx];
    __syncthreads();
    #pragma unroll
    for (int j = 0; j < 32; j += 8) {
        float v = t[tx][ty + j];
        size_t o = (size_t)(n0 + ty + j) * K + k0 + tx;
        bf16 h, l; split_bf16(v, h, l);
        Th[o] = h; Tl[o] = l;
    }
}

// ---------------- Q/K per-head RMSNorm + RoPE (warp per (s,h)) ----------------
__global__ __launch_bounds__(256)
void qkv_transform(const float* __restrict__ rope_cos, const float* __restrict__ rope_sin,
                   const float* __restrict__ qnx, const float* __restrict__ knx,
                   const float* __restrict__ qny, const float* __restrict__ kny) {
    int gw = blockIdx.x * 8 + (threadIdx.x >> 5);
    int lane = threadIdx.x & 31;
    int s = gw / H_, h = gw - s * H_;
    bool isx = (s < NX);
    const float* base = isx ? (g_qkvx + (size_t)s * QKVN) : (g_qkvy + (size_t)(s - NX) * QKVN);
    int d0 = lane * 4;
    int col = h * D_ + d0;

    float4 q = *(const float4*)(base + col);
    float4 k = *(const float4*)(base + DX_ + col);

    float sq = warp_sum(q.x * q.x + q.y * q.y + q.z * q.z + q.w * q.w);
    float sk = warp_sum(k.x * k.x + k.y * k.y + k.z * k.z + k.w * k.w);
    float rq = rsqrtf(sq * (1.f / D_) + 1e-5f);
    float rk = rsqrtf(sk * (1.f / D_) + 1e-5f);

    float4 wq = isx ? *(const float4*)(qnx + d0) : *(const float4*)(qny + d0);
    float4 wk = isx ? *(const float4*)(knx + d0) : *(const float4*)(kny + d0);
    float q0 = q.x * rq * wq.x, q1 = q.y * rq * wq.y, q2 = q.z * rq * wq.z, q3 = q.w * rq * wq.w;
    float k0 = k.x * rk * wk.x, k1 = k.y * rk * wk.y, k2 = k.z * rk * wk.z, k3 = k.w * rk * wk.w;

    if (isx) {
        size_t rbase = ((size_t)s * H_ + h) * (D_ / 2) + (d0 >> 1);
        float2 c = *(const float2*)(rope_cos + rbase);
        float2 sn = *(const float2*)(rope_sin + rbase);
        float e, o_;
        e = q0 * c.x - q1 * sn.x;  o_ = q0 * sn.x + q1 * c.x;  q0 = e; q1 = o_;
        e = q2 * c.y - q3 * sn.y;  o_ = q2 * sn.y + q3 * c.y;  q2 = e; q3 = o_;
        e = k0 * c.x - k1 * sn.x;  o_ = k0 * sn.x + k1 * c.x;  k0 = e; k1 = o_;
        e = k2 * c.y - k3 * sn.y;  o_ = k2 * sn.y + k3 * c.y;  k2 = e; k3 = o_;
    }
    size_t o = ((size_t)h * S_ + s) * D_ + d0;
    store4_split(g_Qh + o, g_Ql + o, q0, q1, q2, q3);
    store4_split(g_Kh + o, g_Kl + o, k0, k1, k2, k3);
}

// ---------------- V transpose to [H][D][S], split ----------------
__global__ void vconv() {
    __shared__ float t[32][33];
    int s0 = blockIdx.x * 32, d0 = blockIdx.y * 32, h = blockIdx.z;
    int tx = threadIdx.x, ty = threadIdx.y;
    #pragma unroll
    for (int j = 0; j < 32; j += 8) {
        int s = s0 + ty + j;
        const float* base = (s < NX) ? (g_qkvx + (size_t)s * QKVN)
                                     : (g_qkvy + (size_t)(s - NX) * QKVN);
        t[ty + j][tx] = base[2 * DX_ + h * D_ + d0 + tx];
    }
    __syncthreads();
    #pragma unroll
    for (int j = 0; j < 32; j += 8) {
        float v = t[tx][ty + j];
        size_t o = ((size_t)h * D_ + d0 + ty + j) * S_ + s0 + tx;
        bf16 hh, ll; split_bf16(v, hh, ll);
        g_Vth[o] = hh; g_Vtl[o] = ll;
    }
}

// ---------------- launch (stream-parallel graph) ----------------
extern "C" void kernel_launch(void* const* d_in, const int* in_sizes, int n_in,
                              void* d_out, int out_size)
{
    const float* x        = (const float*)d_in[0];
    const float* y        = (const float*)d_in[1];
    const float* scale_x  = (const float*)d_in[2];
    const float* scale_y  = (const float*)d_in[3];
    const float* rope_cos = (const float*)d_in[4];
    const float* rope_sin = (const float*)d_in[5];
    const float* Wqkv_x   = (const float*)d_in[6];
    const float* bqkv_x   = (const float*)d_in[7];
    const float* Wqkv_y   = (const float*)d_in[8];
    const float* bqkv_y   = (const float*)d_in[9];
    const float* q_norm_x = (const float*)d_in[10];
    const float* k_norm_x = (const float*)d_in[11];
    const float* q_norm_y = (const float*)d_in[12];
    const float* k_norm_y = (const float*)d_in[13];
    const float* Wproj_x  = (const float*)d_in[14];
    const float* bproj_x  = (const float*)d_in[15];
    const float* Wproj_y  = (const float*)d_in[16];
    const float* bproj_y  = (const float*)d_in[17];
    float* out = (float*)d_out;

    static bool init = false;
    static cudaStream_t s1, s2;
    static cudaEvent_t eFork1, eFork2, eWq, eQx, eQy, eVc, eWp, eF, ePy;
    if (!init) {
        init = true;
        cudaStreamCreateWithFlags(&s1, cudaStreamNonBlocking);
        cudaStreamCreateWithFlags(&s2, cudaStreamNonBlocking);
        cudaEventCreateWithFlags(&eFork1, cudaEventDisableTiming);
        cudaEventCreateWithFlags(&eFork2, cudaEventDisableTiming);
        cudaEventCreateWithFlags(&eWq, cudaEventDisableTiming);
        cudaEventCreateWithFlags(&eQx, cudaEventDisableTiming);
        cudaEventCreateWithFlags(&eQy, cudaEventDisableTiming);
        cudaEventCreateWithFlags(&eVc, cudaEventDisableTiming);
        cudaEventCreateWithFlags(&eWp, cudaEventDisableTiming);
        cudaEventCreateWithFlags(&eF,  cudaEventDisableTiming);
        cudaEventCreateWithFlags(&ePy, cudaEventDisableTiming);
        cudaFuncSetAttribute(mma_gemm, cudaFuncAttributeMaxDynamicSharedMemorySize, GSMEM);
        cudaFuncSetAttribute(mma_gemm_wide, cudaFuncAttributeMaxDynamicSharedMemorySize, WSMEM);
        cudaFuncSetAttribute(flash_attn, cudaFuncAttributeMaxDynamicSharedMemorySize, FSMEM);
    }

    float *qkvx, *qkvy;
    bf16 *xmh, *xml, *ymh, *yml, *wqxh, *wqxl, *wqyh, *wqyl, *wpxh, *wpxl, *wpyh, *wpyl;
    bf16 *Qh, *Ql, *Kh, *Kl, *Vth, *Vtl, *Oh, *Ol;
    cudaGetSymbolAddress((void**)&qkvx, g_qkvx);
    cudaGetSymbolAddress((void**)&qkvy, g_qkvy);
    cudaGetSymbolAddress((void**)&xmh,  g_xm_h);  cudaGetSymbolAddress((void**)&xml, g_xm_l);
    cudaGetSymbolAddress((void**)&ymh,  g_ym_h);  cudaGetSymbolAddress((void**)&yml, g_ym_l);
    cudaGetSymbolAddress((void**)&wqxh, g_WqxT_h); cudaGetSymbolAddress((void**)&wqxl, g_WqxT_l);
    cudaGetSymbolAddress((void**)&wqyh, g_WqyT_h); cudaGetSymbolAddress((void**)&wqyl, g_WqyT_l);
    cudaGetSymbolAddress((void**)&wpxh, g_WpxT_h); cudaGetSymbolAddress((void**)&wpxl, g_WpxT_l);
    cudaGetSymbolAddress((void**)&wpyh, g_WpyT_h); cudaGetSymbolAddress((void**)&wpyl, g_WpyT_l);
    cudaGetSymbolAddress((void**)&Qh, g_Qh);   cudaGetSymbolAddress((void**)&Ql, g_Ql);
    cudaGetSymbolAddress((void**)&Kh, g_Kh);   cudaGetSymbolAddress((void**)&Kl, g_Kl);
    cudaGetSymbolAddress((void**)&Vth, g_Vth); cudaGetSymbolAddress((void**)&Vtl, g_Vtl);
    cudaGetSymbolAddress((void**)&Oh, g_Oh);   cudaGetSymbolAddress((void**)&Ol, g_Ol);

    dim3 t328(32, 8);

    // fork side streams from the captured (default) stream
    cudaEventRecord(eFork1, 0);
    cudaStreamWaitEvent(s1, eFork1, 0);
    cudaEventRecord(eFork2, 0);
    cudaStreamWaitEvent(s2, eFork2, 0);

    // main: rms_x
    rms_mod_split<<<NX, 256>>>(x, scale_x, xmh, xml, DX_, 1e-6f);
    // s1: rms_y, wconv_qkv
    rms_mod_split<<<NY, 256, 0, s1>>>(y, scale_y, ymh, yml, DY_, 1e-6f);
    wconv2<<<dim3(QKVN / 32, DX_ / 32, 2), t328, 0, s1>>>(
        Wqkv_x, wqxh, wqxl, DX_, QKVN,
        Wqkv_y, wqyh, wqyl, DY_, QKVN);
    cudaEventRecord(eWq, s1);
    // s2: wconv_proj
    wconv2<<<dim3(DX_ / 32, DX_ / 32, 2), t328, 0, s2>>>(
        Wproj_x, wpxh, wpxl, DX_, DX_,
        Wproj_y, wpyh, wpyl, DX_, DY_);
    cudaEventRecord(eWp, s2);

    // main: qkv_x
    cudaStreamWaitEvent(0, eWq, 0);
    mma_gemm_wide<<<dim3(QKVN / 256, NX / 128), 256, WSMEM>>>(
        xmh, xml, wqxh, wqxl, bqkv_x, qkvx, DX_, DX_, DX_, QKVN);
    cudaEventRecord(eQx, 0);

    // s1: qkv_y
    mma_gemm<<<dim3(QKVN / 128, NY / 128, 1), 256, GSMEM, s1>>>(
        ymh, yml, wqyh, wqyl, bqkv_y, qkvy, nullptr, nullptr,
        DY_, DY_, DY_, QKVN, 0, 0, 0);
    cudaEventRecord(eQy, s1);

    // main: qkv_transform
    cudaStreamWaitEvent(0, eQy, 0);
    qkv_transform<<<(S_ * H_) / 8, 256>>>(rope_cos, rope_sin,
                                          q_norm_x, k_norm_x, q_norm_y, k_norm_y);
    // s1: vconv (concurrent with transform)
    cudaStreamWaitEvent(s1, eQx, 0);
    vconv<<<dim3(S_ / 32, D_ / 32, H_), t328, 0, s1>>>();
    cudaEventRecord(eVc, s1);

    // main: flash
    cudaStreamWaitEvent(0, eVc, 0);
    flash_attn<<<dim3(S_ / 64, H_), 256, FSMEM>>>(Qh, Ql, Kh, Kl, Vth, Vtl, Oh, Ol);
    cudaEventRecord(eF, 0);

    // main: proj_x
    cudaStreamWaitEvent(0, eWp, 0);
    mma_gemm_wide<<<dim3(DX_ / 256, NX / 128), 256, WSMEM>>>(
        Oh, Ol, wpxh, wpxl, bproj_x, out, DX_, DX_, DX_, DX_);

    // s1: proj_y (concurrent with proj_x)
    cudaStreamWaitEvent(s1, eF, 0);
    cudaStreamWaitEvent(s1, eWp, 0);
    mma_gemm<<<dim3(DY_ / 128, NY / 128, 1), 256, GSMEM, s1>>>(
        Oh + (size_t)NX * DX_, Ol + (size_t)NX * DX_, wpyh, wpyl, bproj_y,
        out + (size_t)NX * DX_, nullptr, nullptr,
        DX_, DX_, DX_, DY_, 0, 0, 0);
    cudaEventRecord(ePy, s1);

    // join side streams
    cudaStreamWaitEvent(0, ePy, 0);
}

// round 15
// speedup vs baseline: 1.5335x; 1.5335x over previous
#include <cuda_runtime.h>
#include <cuda_bf16.h>
#include <cstdint>
#include <math.h>

#define H_    12
#define D_    128
#define NX    2048
#define NY    256
#define S_    2304
#define DX_   1536
#define DY_   768
#define QKVN  4608

typedef __nv_bfloat16 bf16;

// ---------------- scratch (static device globals; no allocation) ----------------
__device__ __align__(256) float g_qkvx[(size_t)NX * QKVN];
__device__ __align__(256) float g_qkvy[(size_t)NY * QKVN];
__device__ __align__(256) bf16 g_xm_h[(size_t)NX * DX_],  g_xm_l[(size_t)NX * DX_];
__device__ __align__(256) bf16 g_ym_h[(size_t)NY * DY_],  g_ym_l[(size_t)NY * DY_];
__device__ __align__(256) bf16 g_WqxT_h[(size_t)QKVN * DX_], g_WqxT_l[(size_t)QKVN * DX_];
__device__ __align__(256) bf16 g_WqyT_h[(size_t)QKVN * DY_], g_WqyT_l[(size_t)QKVN * DY_];
__device__ __align__(256) bf16 g_WpxT_h[(size_t)DX_ * DX_],  g_WpxT_l[(size_t)DX_ * DX_];
__device__ __align__(256) bf16 g_WpyT_h[(size_t)DY_ * DX_],  g_WpyT_l[(size_t)DY_ * DX_];
__device__ __align__(256) bf16 g_Qh[(size_t)H_ * S_ * D_], g_Ql[(size_t)H_ * S_ * D_];
__device__ __align__(256) bf16 g_Kh[(size_t)H_ * S_ * D_], g_Kl[(size_t)H_ * S_ * D_];
__device__ __align__(256) bf16 g_Vth[(size_t)H_ * D_ * S_], g_Vtl[(size_t)H_ * D_ * S_];
__device__ __align__(256) bf16 g_Oh[(size_t)S_ * DX_],      g_Ol[(size_t)S_ * DX_];

// ---------------- small helpers ----------------
__device__ __forceinline__ float warp_sum(float v) {
    #pragma unroll
    for (int o = 16; o; o >>= 1) v += __shfl_xor_sync(0xffffffffu, v, o);
    return v;
}
__device__ float block_red(float v, float* sbuf, bool ismax) {
    #pragma unroll
    for (int o = 16; o; o >>= 1)
        v = ismax ? fmaxf(v, __shfl_xor_sync(0xffffffffu, v, o))
                  : v + __shfl_xor_sync(0xffffffffu, v, o);
    int w = threadIdx.x >> 5, nw = blockDim.x >> 5;
    if ((threadIdx.x & 31) == 0) sbuf[w] = v;
    __syncthreads();
    if (threadIdx.x < 32) {
        float t = (threadIdx.x < nw) ? sbuf[threadIdx.x] : (ismax ? -1e30f : 0.f);
        #pragma unroll
        for (int o = 16; o; o >>= 1)
            t = ismax ? fmaxf(t, __shfl_xor_sync(0xffffffffu, t, o))
                      : t + __shfl_xor_sync(0xffffffffu, t, o);
        if (threadIdx.x == 0) sbuf[0] = t;
    }
    __syncthreads();
    float r = sbuf[0];
    __syncthreads();
    return r;
}
__device__ __forceinline__ void split_bf16(float v, bf16& h, bf16& l) {
    h = __float2bfloat16(v);
    l = __float2bfloat16(v - __bfloat162float(h));
}
__device__ __forceinline__ uint32_t pack_hi2(float a, float b, uint32_t& lo) {
    bf16 h0, l0, h1, l1;
    split_bf16(a, h0, l0); split_bf16(b, h1, l1);
    __nv_bfloat162 hp(h0, h1), lp(l0, l1);
    lo = *(uint32_t*)&lp;
    return *(uint32_t*)&hp;
}
__device__ __forceinline__ void store4_split(bf16* dh, bf16* dl,
                                             float v0, float v1, float v2, float v3) {
    uint32_t l0, l1;
    uint32_t h0 = pack_hi2(v0, v1, l0);
    uint32_t h1 = pack_hi2(v2, v3, l1);
    *(uint2*)dh = make_uint2(h0, h1);
    *(uint2*)dl = make_uint2(l0, l1);
}
__device__ __forceinline__ uint32_t smem_u32(const void* p) {
    return (uint32_t)__cvta_generic_to_shared(p);
}
__device__ __forceinline__ void cp16(uint32_t s, const void* g) {
    asm volatile("cp.async.cg.shared.global [%0], [%1], 16;" :: "r"(s), "l"(g));
}
__device__ __forceinline__ void ldmx4(uint32_t* r, uint32_t a) {
    asm volatile("ldmatrix.sync.aligned.m8n8.x4.shared.b16 {%0,%1,%2,%3}, [%4];"
                 : "=r"(r[0]), "=r"(r[1]), "=r"(r[2]), "=r"(r[3]) : "r"(a));
}
__device__ __forceinline__ void mma16816(float* c, const uint32_t* a, uint32_t b0, uint32_t b1) {
    asm volatile(
        "mma.sync.aligned.m16n8k16.row.col.f32.bf16.bf16.f32 "
        "{%0,%1,%2,%3}, {%4,%5,%6,%7}, {%8,%9}, {%0,%1,%2,%3};"
        : "+f"(c[0]), "+f"(c[1]), "+f"(c[2]), "+f"(c[3])
        : "r"(a[0]), "r"(a[1]), "r"(a[2]), "r"(a[3]), "r"(b0), "r"(b1));
}

// ---------------- bf16x3 HMMA GEMM, narrow 128x128 ----------------
#define PADB   80
#define TILEB  (128 * PADB)
#define STAGEB (4 * TILEB)
#define GSMEM  (2 * STAGEB)

__global__ __launch_bounds__(256, 2)
void mma_gemm(const bf16* __restrict__ Ah, const bf16* __restrict__ Al,
              const bf16* __restrict__ Bh, const bf16* __restrict__ Bl,
              const float* __restrict__ bias,
              float* __restrict__ Cf, bf16* __restrict__ Ch, bf16* __restrict__ Cl,
              int K, int lda, int ldb, int ldc,
              long sA, long sB, long sC)
{
    extern __shared__ char smem[];
    uint32_t sb = smem_u32(smem);
    int tid = threadIdx.x, wid = tid >> 5, lane = tid & 31;
    int wr = wid >> 1, wc = wid & 1;

    const bf16* pAh = Ah + (size_t)blockIdx.z * sA + (size_t)blockIdx.y * 128 * lda;
    const bf16* pAl = Al + (size_t)blockIdx.z * sA + (size_t)blockIdx.y * 128 * lda;
    const bf16* pBh = Bh + (size_t)blockIdx.z * sB + (size_t)blockIdx.x * 128 * ldb;
    const bf16* pBl = Bl + (size_t)blockIdx.z * sB + (size_t)blockIdx.x * 128 * ldb;

    const int NC = K >> 5;

    auto load_stage = [&](int st, int k0) {
        uint32_t s0 = sb + st * STAGEB;
        const bf16* srcs[4] = {pAh, pAl, pBh, pBl};
        #pragma unroll
        for (int t = 0; t < 4; t++) {
            int ldt = (t < 2) ? lda : ldb;
            const char* gb = (const char*)srcs[t] + (size_t)k0 * 2;
            #pragma unroll
            for (int i = 0; i < 2; i++) {
                int idx = tid + (i << 8);
                int row = idx >> 2, ch = idx & 3;
                cp16(s0 + t * TILEB + row * PADB + ch * 16,
                     gb + (size_t)row * ldt * 2 + ch * 16);
            }
        }
        asm volatile("cp.async.commit_group;");
    };

    float acc[2][8][4];
    #pragma unroll
    for (int i = 0; i < 2; i++)
        #pragma unroll
        for (int j = 0; j < 8; j++)
            #pragma unroll
            for (int r = 0; r < 4; r++) acc[i][j][r] = 0.f;

    int r8 = lane & 7, seg = lane >> 3;
    int a_row = (seg & 1) * 8 + r8;
    int a_kb  = (seg >> 1) * 16;
    int b_row = (seg >> 1) * 8 + r8;
    int b_kb  = (seg & 1) * 16;

    load_stage(0, 0);

    for (int i = 0; i < NC; i++) {
        asm volatile("cp.async.wait_group 0;");
        __syncthreads();
        if (i + 1 < NC) load_stage((i + 1) & 1, (i + 1) << 5);

        uint32_t base = sb + (i & 1) * STAGEB;
        #pragma unroll
        for (int ks = 0; ks < 2; ks++) {
            int kb = ks * 32;
            uint32_t ah[2][4], al[2][4], bh[4][4], bl[4][4];
            #pragma unroll
            for (int mi = 0; mi < 2; mi++) {
                uint32_t ad = base + (wr * 32 + mi * 16 + a_row) * PADB + kb + a_kb;
                ldmx4(ah[mi], ad);
                ldmx4(al[mi], ad + TILEB);
            }
            #pragma unroll
            for (int nj = 0; nj < 4; nj++) {
                uint32_t bd = base + 2 * TILEB + (wc * 64 + nj * 16 + b_row) * PADB + kb + b_kb;
                ldmx4(bh[nj], bd);
                ldmx4(bl[nj], bd + TILEB);
            }
            #pragma unroll
            for (int mi = 0; mi < 2; mi++)
                #pragma unroll
                for (int nt = 0; nt < 8; nt++) {
                    int nj = nt >> 1, hf = (nt & 1) * 2;
                    mma16816(acc[mi][nt], ah[mi], bh[nj][hf], bh[nj][hf + 1]);
                    mma16816(acc[mi][nt], ah[mi], bl[nj][hf], bl[nj][hf + 1]);
                    mma16816(acc[mi][nt], al[mi], bh[nj][hf], bh[nj][hf + 1]);
                }
        }
    }

    int brow = blockIdx.y * 128 + wr * 32 + (lane >> 2);
    int bcol = blockIdx.x * 128 + wc * 64 + (lane & 3) * 2;
    #pragma unroll
    for (int mi = 0; mi < 2; mi++)
        #pragma unroll
        for (int nt = 0; nt < 8; nt++)
            #pragma unroll
            for (int rh = 0; rh < 2; rh++) {
                int rr = brow + mi * 16 + rh * 8;
                int cc = bcol + nt * 8;
                float v0 = acc[mi][nt][rh * 2 + 0];
                float v1 = acc[mi][nt][rh * 2 + 1];
                if (bias) { v0 += __ldg(bias + cc); v1 += __ldg(bias + cc + 1); }
                size_t ci = (size_t)blockIdx.z * sC + (size_t)rr * ldc + cc;
                if (Cf) *(float2*)(Cf + ci) = make_float2(v0, v1);
                if (Ch) {
                    bf16 h0, l0, h1, l1;
                    split_bf16(v0, h0, l0); split_bf16(v1, h1, l1);
                    *(__nv_bfloat162*)(Ch + ci) = __nv_bfloat162(h0, h1);
                    *(__nv_bfloat162*)(Cl + ci) = __nv_bfloat162(l0, l1);
                }
            }
}

// ---------------- bf16x3 HMMA GEMM, wide 128x256 ----------------
#define WPAD  80
#define WTA   (128 * WPAD)
#define WTB   (256 * WPAD)
#define WSTG  (2 * WTA + 2 * WTB)
#define WSMEM (3 * WSTG)

__global__ __launch_bounds__(256, 1)
void mma_gemm_wide(const bf16* __restrict__ Ah, const bf16* __restrict__ Al,
                   const bf16* __restrict__ Bh, const bf16* __restrict__ Bl,
                   const float* __restrict__ bias, float* __restrict__ Cf,
                   int K, int lda, int ldb, int ldc)
{
    extern __shared__ char smem[];
    uint32_t sb = smem_u32(smem);
    int tid = threadIdx.x, wid = tid >> 5, lane = tid & 31;
    int wr = wid & 1, wc = wid >> 1;

    const bf16* pAh = Ah + (size_t)blockIdx.y * 128 * lda;
    const bf16* pAl = Al + (size_t)blockIdx.y * 128 * lda;
    const bf16* pBh = Bh + (size_t)blockIdx.x * 256 * ldb;
    const bf16* pBl = Bl + (size_t)blockIdx.x * 256 * ldb;

    const int NC = K >> 5;

    auto load_stage = [&](int st, int k0) {
        uint32_t s0 = sb + st * WSTG;
        const char* gah = (const char*)pAh + (size_t)k0 * 2;
        const char* gal = (const char*)pAl + (size_t)k0 * 2;
        #pragma unroll
        for (int i = 0; i < 2; i++) {
            int idx = tid + (i << 8);
            int row = idx >> 2, ch = idx & 3;
            size_t go = (size_t)row * lda * 2 + ch * 16;
            cp16(s0 + row * WPAD + ch * 16,        gah + go);
            cp16(s0 + WTA + row * WPAD + ch * 16,  gal + go);
        }
        const char* gbh = (const char*)pBh + (size_t)k0 * 2;
        const char* gbl = (const char*)pBl + (size_t)k0 * 2;
        #pragma unroll
        for (int i = 0; i < 4; i++) {
            int idx = tid + (i << 8);
            int row = idx >> 2, ch = idx & 3;
            size_t go = (size_t)row * ldb * 2 + ch * 16;
            cp16(s0 + 2 * WTA + row * WPAD + ch * 16,       gbh + go);
            cp16(s0 + 2 * WTA + WTB + row * WPAD + ch * 16, gbl + go);
        }
        asm volatile("cp.async.commit_group;");
    };

    float acc[4][8][4];
    #pragma unroll
    for (int i = 0; i < 4; i++)
        #pragma unroll
        for (int j = 0; j < 8; j++)
            #pragma unroll
            for (int r = 0; r < 4; r++) acc[i][j][r] = 0.f;

    int r8 = lane & 7, seg = lane >> 3;
    int a_row = (seg & 1) * 8 + r8;
    int a_kb  = (seg >> 1) * 16;
    int b_row = (seg >> 1) * 8 + r8;
    int b_kb  = (seg & 1) * 16;

    load_stage(0, 0);
    load_stage(1, 32);

    for (int i = 0; i < NC; i++) {
        if (i < NC - 1) { asm volatile("cp.async.wait_group 1;"); }
        else            { asm volatile("cp.async.wait_group 0;"); }
        __syncthreads();
        if (i + 2 < NC) load_stage((i + 2) % 3, (i + 2) << 5);

        uint32_t base = sb + (i % 3) * WSTG;
        #pragma unroll
        for (int ks = 0; ks < 2; ks++) {
            int kb = ks * 32;
            uint32_t ah[4][4], al[4][4];
            #pragma unroll
            for (int mi = 0; mi < 4; mi++) {
                uint32_t ad = base + (wr * 64 + mi * 16 + a_row) * WPAD + kb + a_kb;
                ldmx4(ah[mi], ad);
                ldmx4(al[mi], ad + WTA);
            }
            #pragma unroll
            for (int nj = 0; nj < 4; nj++) {
                uint32_t bh[4], bl[4];
                uint32_t bd = base + 2 * WTA + (wc * 64 + nj * 16 + b_row) * WPAD + kb + b_kb;
                ldmx4(bh, bd);
                ldmx4(bl, bd + WTB);
                #pragma unroll
                for (int mi = 0; mi < 4; mi++)
                    #pragma unroll
                    for (int half = 0; half < 2; half++) {
                        int nt = nj * 2 + half, hf = half * 2;
                        mma16816(acc[mi][nt], ah[mi], bh[hf], bh[hf + 1]);
                        mma16816(acc[mi][nt], ah[mi], bl[hf], bl[hf + 1]);
                        mma16816(acc[mi][nt], al[mi], bh[hf], bh[hf + 1]);
                    }
            }
        }
    }

    int brow = blockIdx.y * 128 + wr * 64 + (lane >> 2);
    int bcol = blockIdx.x * 256 + wc * 64 + (lane & 3) * 2;
    #pragma unroll
    for (int mi = 0; mi < 4; mi++)
        #pragma unroll
        for (int nt = 0; nt < 8; nt++)
            #pragma unroll
            for (int rh = 0; rh < 2; rh++) {
                int rr = brow + mi * 16 + rh * 8;
                int cc = bcol + nt * 8;
                float v0 = acc[mi][nt][rh * 2 + 0];
                float v1 = acc[mi][nt][rh * 2 + 1];
                if (bias) { v0 += __ldg(bias + cc); v1 += __ldg(bias + cc + 1); }
                *(float2*)(Cf + (size_t)rr * ldc + cc) = make_float2(v0, v1);
            }
}

// ---------------- fused flash attention (pipelined waits: wait-before-use) ----------------
#define QPAD  272
#define KPAD  272
#define VPAD  144
#define QTB   (64 * QPAD)
#define KTB   (64 * KPAD)
#define VTB   (128 * VPAD)
#define STGB  (2 * KTB + 2 * VTB)
#define FSMEM (2 * QTB + 2 * STGB)

__global__ __launch_bounds__(256, 1)
void flash_attn(const bf16* __restrict__ Qh_, const bf16* __restrict__ Ql_,
                const bf16* __restrict__ Kh_, const bf16* __restrict__ Kl_,
                const bf16* __restrict__ Vh_, const bf16* __restrict__ Vl_,
                bf16* __restrict__ Oh_, bf16* __restrict__ Ol_)
{
    extern __shared__ char smem[];
    uint32_t sb = smem_u32(smem);
    int tid = threadIdx.x, wid = tid >> 5, lane = tid & 31;
    int wg = wid >> 2, wid4 = wid & 3, tid4 = tid & 127;
    int h = blockIdx.y;
    int q0 = blockIdx.x * 64;

    const bf16* Qhb = Qh_ + ((size_t)h * S_ + q0) * D_;
    const bf16* Qlb = Ql_ + ((size_t)h * S_ + q0) * D_;
    const bf16* Khb = Kh_ + (size_t)h * S_ * D_;
    const bf16* Klb = Kl_ + (size_t)h * S_ * D_;
    const bf16* Vhb = Vh_ + (size_t)h * D_ * S_;
    const bf16* Vlb = Vl_ + (size_t)h * D_ * S_;

    const uint32_t Qs = sb, STG0 = sb + 2 * QTB;
    const uint32_t MYB = STG0 + (uint32_t)wg * STGB;

    #pragma unroll
    for (int i = 0; i < 4; i++) {
        int c = tid + (i << 8);
        int row = c >> 4, ch = c & 15;
        cp16(Qs + row * QPAD + ch * 16,        (const char*)Qhb + (size_t)row * 256 + ch * 16);
        cp16(Qs + QTB + row * QPAD + ch * 16,  (const char*)Qlb + (size_t)row * 256 + ch * 16);
    }
    auto load_K = [&](int blk) {
        const char* kh = (const char*)(Khb + (size_t)blk * 64 * D_);
        const char* kl = (const char*)(Klb + (size_t)blk * 64 * D_);
        #pragma unroll
        for (int i = 0; i < 8; i++) {
            int c = tid4 + (i << 7);
            int row = c >> 4, ch = c & 15;
            cp16(MYB + row * KPAD + ch * 16,       kh + (size_t)row * 256 + ch * 16);
            cp16(MYB + KTB + row * KPAD + ch * 16, kl + (size_t)row * 256 + ch * 16);
        }
        asm volatile("cp.async.commit_group;");
    };
    auto load_V = [&](int blk) {
        const char* vh = (const char*)(Vhb + (size_t)blk * 64);
        const char* vl = (const char*)(Vlb + (size_t)blk * 64);
        #pragma unroll
        for (int i = 0; i < 8; i++) {
            int c = tid4 + (i << 7);
            int row = c >> 3, ch = c & 7;
            cp16(MYB + 2 * KTB + row * VPAD + ch * 16,       vh + (size_t)row * S_ * 2 + ch * 16);
            cp16(MYB + 2 * KTB + VTB + row * VPAD + ch * 16, vl + (size_t)row * S_ * 2 + ch * 16);
        }
        asm volatile("cp.async.commit_group;");
    };
    // group sequence per thread: [Q+K(0)], [V(0)], [K(1)], [V(1)], ...
    load_K(wg);
    load_V(wg);
    asm volatile("cp.async.wait_group 1;");
    __syncthreads();

    int r8 = lane & 7, seg = lane >> 3;
    int a_row = (seg & 1) * 8 + r8;
    int a_kb  = (seg >> 1) * 16;
    int b_row = (seg >> 1) * 8 + r8;
    int b_kb  = (seg & 1) * 16;

    float o[16][4];
    #pragma unroll
    for (int t = 0; t < 16; t++)
        #pragma unroll
        for (int r = 0; r < 4; r++) o[t][r] = 0.f;
    float m0 = -1e30f, m1 = -1e30f, l0 = 0.f, l1 = 0.f;
    const float sc = 0.08838834764831845f;
    const int bar_id = 1 + wg;

    const int NIT = (S_ / 64) / 2;
    for (int it = 0; it < NIT; it++) {
        uint32_t Ks = MYB;
        uint32_t Vs = MYB + 2 * KTB;
        bool more = (it + 1 < NIT);

        // need K(it): outstanding = {K(it), V(it)} -> allow 1 pending
        asm volatile("cp.async.wait_group 1;");
        asm volatile("bar.sync %0, 128;" :: "r"(bar_id) : "memory");

        float st[8][4];
        #pragma unroll
        for (int t = 0; t < 8; t++)
            #pragma unroll
            for (int r = 0; r < 4; r++) st[t][r] = 0.f;

        #pragma unroll
        for (int ks = 0; ks < 8; ks++) {
            int kb = ks * 32;
            uint32_t qh[4], ql[4], kh[4][4], kl[4][4];
            uint32_t qa = Qs + (wid4 * 16 + a_row) * QPAD + kb + a_kb;
            ldmx4(qh, qa);
            ldmx4(ql, qa + QTB);
            #pragma unroll
            for (int nj = 0; nj < 4; nj++) {
                uint32_t ka = Ks + (nj * 16 + b_row) * KPAD + kb + b_kb;
                ldmx4(kh[nj], ka);
                ldmx4(kl[nj], ka + KTB);
            }
            #pragma unroll
            for (int nt = 0; nt < 8; nt++) {
                int nj = nt >> 1, hf = (nt & 1) * 2;
                mma16816(st[nt], qh, kh[nj][hf], kh[nj][hf + 1]);
                mma16816(st[nt], qh, kl[nj][hf], kl[nj][hf + 1]);
                mma16816(st[nt], ql, kh[nj][hf], kh[nj][hf + 1]);
            }
        }

        // K consumed by all warps of this wg -> refill (no wait here)
        asm volatile("bar.sync %0, 128;" :: "r"(bar_id) : "memory");
        if (more) load_K(wg + 2 * (it + 1));

        // online softmax (overlaps K(it+1) flight)
        float bm0 = -1e30f, bm1 = -1e30f;
        #pragma unroll
        for (int t = 0; t < 8; t++) {
            bm0 = fmaxf(bm0, fmaxf(st[t][0], st[t][1]));
            bm1 = fmaxf(bm1, fmaxf(st[t][2], st[t][3]));
        }
        #pragma unroll
        for (int off = 1; off <= 2; off <<= 1) {
            bm0 = fmaxf(bm0, __shfl_xor_sync(0xffffffffu, bm0, off));
            bm1 = fmaxf(bm1, __shfl_xor_sync(0xffffffffu, bm1, off));
        }
        float nm0 = fmaxf(m0, bm0), nm1 = fmaxf(m1, bm1);
        float al0 = __expf((m0 - nm0) * sc), al1 = __expf((m1 - nm1) * sc);
        float ps0 = 0.f, ps1 = 0.f;
        #pragma unroll
        for (int t = 0; t < 8; t++) {
            st[t][0] = __expf((st[t][0] - nm0) * sc);
            st[t][1] = __expf((st[t][1] - nm0) * sc);
            st[t][2] = __expf((st[t][2] - nm1) * sc);
            st[t][3] = __expf((st[t][3] - nm1) * sc);
            ps0 += st[t][0] + st[t][1];
            ps1 += st[t][2] + st[t][3];
        }
        #pragma unroll
        for (int off = 1; off <= 2; off <<= 1) {
            ps0 += __shfl_xor_sync(0xffffffffu, ps0, off);
            ps1 += __shfl_xor_sync(0xffffffffu, ps1, off);
        }
        l0 = l0 * al0 + ps0;
        l1 = l1 * al1 + ps1;
        m0 = nm0; m1 = nm1;
        #pragma unroll
        for (int t = 0; t < 16; t++) {
            o[t][0] *= al0; o[t][1] *= al0;
            o[t][2] *= al1; o[t][3] *= al1;
        }

        // need V(it): outstanding = {V(it), K(it+1)?}
        if (more) { asm volatile("cp.async.wait_group 1;"); }
        else      { asm volatile("cp.async.wait_group 0;"); }
        asm volatile("bar.sync %0, 128;" :: "r"(bar_id) : "memory");

        #pragma unroll
        for (int g = 0; g < 4; g++) {
            uint32_t aph[4], apl[4];
            #pragma unroll
            for (int half = 0; half < 2; half++) {
                float* s0 = st[2 * g + half];
                aph[2 * half + 0] = pack_hi2(s0[0], s0[1], apl[2 * half + 0]);
                aph[2 * half + 1] = pack_hi2(s0[2], s0[3], apl[2 * half + 1]);
            }
            #pragma unroll
            for (int nj = 0; nj < 8; nj++) {
                uint32_t vh[4], vl[4];
                uint32_t va = Vs + (nj * 16 + b_row) * VPAD + g * 32 + b_kb;
                ldmx4(vh, va);
                ldmx4(vl, va + VTB);
                #pragma unroll
                for (int half = 0; half < 2; half++) {
                    int t = nj * 2 + half;
                    int hf = half * 2;
                    mma16816(o[t], aph, vh[hf], vh[hf + 1]);
                    mma16816(o[t], apl, vh[hf], vh[hf + 1]);
                    mma16816(o[t], aph, vl[hf], vl[hf + 1]);
                }
            }
        }

        // V consumed -> refill (next iter waits before use)
        asm volatile("bar.sync %0, 128;" :: "r"(bar_id) : "memory");
        if (more) load_V(wg + 2 * (it + 1));
    }

    float* sf = (float*)smem;
    __syncthreads();
    if (wg == 1) {
        float* dml = sf + tid4 * 4;
        dml[0] = m0; dml[1] = m1; dml[2] = l0; dml[3] = l1;
        float* doo = sf + 512 + tid4 * 64;
        #pragma unroll
        for (int t = 0; t < 16; t++)
            *(float4*)(doo + t * 4) = make_float4(o[t][0], o[t][1], o[t][2], o[t][3]);
    }
    __syncthreads();
    if (wg == 0) {
        float* pml = sf + tid4 * 4;
        float pm0 = pml[0], pm1 = pml[1], pl0 = pml[2], pl1 = pml[3];
        float* poo = sf + 512 + tid4 * 64;
        float M0 = fmaxf(m0, pm0), M1 = fmaxf(m1, pm1);
        float w00 = __expf((m0 - M0) * sc), w01 = __expf((pm0 - M0) * sc);
        float w10 = __expf((m1 - M1) * sc), w11 = __expf((pm1 - M1) * sc);
        float L0 = l0 * w00 + pl0 * w01;
        float L1 = l1 * w10 + pl1 * w11;
        float i0 = 1.f / L0, i1 = 1.f / L1;
        int sr0 = q0 + wid4 * 16 + (lane >> 2);
        #pragma unroll
        for (int t = 0; t < 16; t++) {
            float4 po = *(float4*)(poo + t * 4);
            float v0 = (o[t][0] * w00 + po.x * w01) * i0;
            float v1 = (o[t][1] * w00 + po.y * w01) * i0;
            float v2 = (o[t][2] * w10 + po.z * w11) * i1;
            float v3 = (o[t][3] * w10 + po.w * w11) * i1;
            int cc = h * 128 + t * 8 + (lane & 3) * 2;
            bf16 h0, lo0, h1, lo1;
            split_bf16(v0, h0, lo0); split_bf16(v1, h1, lo1);
            size_t ci = (size_t)sr0 * DX_ + cc;
            *(__nv_bfloat162*)(Oh_ + ci) = __nv_bfloat162(h0, h1);
            *(__nv_bfloat162*)(Ol_ + ci) = __nv_bfloat162(lo0, lo1);
            split_bf16(v2, h0, lo0); split_bf16(v3, h1, lo1);
            ci = (size_t)(sr0 + 8) * DX_ + cc;
            *(__nv_bfloat162*)(Oh_ + ci) = __nv_bfloat162(h0, h1);
            *(__nv_bfloat162*)(Ol_ + ci) = __nv_bfloat162(lo0, lo1);
        }
    }
}

// ---------------- RMSNorm + modulation, split hi/lo ----------------
__global__ void rms_mod_split(const float* __restrict__ X, const float* __restrict__ sc,
                              bf16* __restrict__ oh, bf16* __restrict__ ol, int Dm, float eps) {
    __shared__ float sbuf[32];
    size_t row = blockIdx.x;
    const float* xr = X + row * Dm;
    float ss = 0.f;
    for (int i = threadIdx.x; i < Dm; i += blockDim.x) { float t = xr[i]; ss += t * t; }
    ss = block_red(ss, sbuf, false);
    float r = rsqrtf(ss / (float)Dm + eps);
    for (int i = threadIdx.x; i < Dm; i += blockDim.x) {
        float v = xr[i] * r * (1.f + sc[i]);
        bf16 h, l; split_bf16(v, h, l);
        oh[row * Dm + i] = h; ol[row * Dm + i] = l;
    }
}

// ---------------- dual weight transpose + split ----------------
__global__ void wconv2(const float* __restrict__ W0, bf16* __restrict__ Th0, bf16* __restrict__ Tl0,
                       int K0, int N0,
                       const float* __restrict__ W1, bf16* __restrict__ Th1, bf16* __restrict__ Tl1,
                       int K1, int N1) {
    const float* W; bf16 *Th, *Tl; int K, N;
    if (blockIdx.z == 0) { W = W0; Th = Th0; Tl = Tl0; K = K0; N = N0; }
    else                 { W = W1; Th = Th1; Tl = Tl1; K = K1; N = N1; }
    int n0 = blockIdx.x * 32, k0 = blockIdx.y * 32;
    if (n0 >= N || k0 >= K) return;
    __shared__ float t[32][33];
    int tx = threadIdx.x, ty = threadIdx.y;
    #pragma unroll
    for (int j = 0; j < 32; j += 8)
        t[ty + j][tx] = W[(size_t)(k0 + ty + j) * N + n0 + tx];
    __syncthreads();
    #pragma unroll
    for (int j = 0; j < 32; j += 8) {
        float v = t[tx][ty + j];
        size_t o = (size_t)(n0 + ty + j) * K + k0 + tx;
        bf16 h, l; split_bf16(v, h, l);
        Th[o] = h; Tl[o] = l;
    }
}

// ---------------- Q/K per-head RMSNorm + RoPE (warp per (s,h)) ----------------
__global__ __launch_bounds__(256)
void qkv_transform(const float* __restrict__ rope_cos, const float* __restrict__ rope_sin,
                   const float* __restrict__ qnx, const float* __restrict__ knx,
                   const float* __restrict__ qny, const float* __restrict__ kny) {
    int gw = blockIdx.x * 8 + (threadIdx.x >> 5);
    int lane = threadIdx.x & 31;
    int s = gw / H_, h = gw - s * H_;
    bool isx = (s < NX);
    const float* base = isx ? (g_qkvx + (size_t)s * QKVN) : (g_qkvy + (size_t)(s - NX) * QKVN);
    int d0 = lane * 4;
    int col = h * D_ + d0;

    float4 q = *(const float4*)(base + col);
    float4 k = *(const float4*)(base + DX_ + col);

    float sq = warp_sum(q.x * q.x + q.y * q.y + q.z * q.z + q.w * q.w);
    float sk = warp_sum(k.x * k.x + k.y * k.y + k.z * k.z + k.w * k.w);
    float rq = rsqrtf(sq * (1.f / D_) + 1e-5f);
    float rk = rsqrtf(sk * (1.f / D_) + 1e-5f);

    float4 wq = isx ? *(const float4*)(qnx + d0) : *(const float4*)(qny + d0);
    float4 wk = isx ? *(const float4*)(knx + d0) : *(const float4*)(kny + d0);
    float q0 = q.x * rq * wq.x, q1 = q.y * rq * wq.y, q2 = q.z * rq * wq.z, q3 = q.w * rq * wq.w;
    float k0 = k.x * rk * wk.x, k1 = k.y * rk * wk.y, k2 = k.z * rk * wk.z, k3 = k.w * rk * wk.w;

    if (isx) {
        size_t rbase = ((size_t)s * H_ + h) * (D_ / 2) + (d0 >> 1);
        float2 c = *(const float2*)(rope_cos + rbase);
        float2 sn = *(const float2*)(rope_sin + rbase);
        float e, o_;
        e = q0 * c.x - q1 * sn.x;  o_ = q0 * sn.x + q1 * c.x;  q0 = e; q1 = o_;
        e = q2 * c.y - q3 * sn.y;  o_ = q2 * sn.y + q3 * c.y;  q2 = e; q3 = o_;
        e = k0 * c.x - k1 * sn.x;  o_ = k0 * sn.x + k1 * c.x;  k0 = e; k1 = o_;
        e = k2 * c.y - k3 * sn.y;  o_ = k2 * sn.y + k3 * c.y;  k2 = e; k3 = o_;
    }
    size_t o = ((size_t)h * S_ + s) * D_ + d0;
    store4_split(g_Qh + o, g_Ql + o, q0, q1, q2, q3);
    store4_split(g_Kh + o, g_Kl + o, k0, k1, k2, k3);
}

// ---------------- V transpose to [H][D][S], split ----------------
__global__ void vconv() {
    __shared__ float t[32][33];
    int s0 = blockIdx.x * 32, d0 = blockIdx.y * 32, h = blockIdx.z;
    int tx = threadIdx.x, ty = threadIdx.y;
    #pragma unroll
    for (int j = 0; j < 32; j += 8) {
        int s = s0 + ty + j;
        const float* base = (s < NX) ? (g_qkvx + (size_t)s * QKVN)
                                     : (g_qkvy + (size_t)(s - NX) * QKVN);
        t[ty + j][tx] = base[2 * DX_ + h * D_ + d0 + tx];
    }
    __syncthreads();
    #pragma unroll
    for (int j = 0; j < 32; j += 8) {
        float v = t[tx][ty + j];
        size_t o = ((size_t)h * D_ + d0 + ty + j) * S_ + s0 + tx;
        bf16 hh, ll; split_bf16(v, hh, ll);
        g_Vth[o] = hh; g_Vtl[o] = ll;
    }
}

// ---------------- launch (stream-parallel graph) ----------------
extern "C" void kernel_launch(void* const* d_in, const int* in_sizes, int n_in,
                              void* d_out, int out_size)
{
    const float* x        = (const float*)d_in[0];
    const float* y        = (const float*)d_in[1];
    const float* scale_x  = (const float*)d_in[2];
    const float* scale_y  = (const float*)d_in[3];
    const float* rope_cos = (const float*)d_in[4];
    const float* rope_sin = (const float*)d_in[5];
    const float* Wqkv_x   = (const float*)d_in[6];
    const float* bqkv_x   = (const float*)d_in[7];
    const float* Wqkv_y   = (const float*)d_in[8];
    const float* bqkv_y   = (const float*)d_in[9];
    const float* q_norm_x = (const float*)d_in[10];
    const float* k_norm_x = (const float*)d_in[11];
    const float* q_norm_y = (const float*)d_in[12];
    const float* k_norm_y = (const float*)d_in[13];
    const float* Wproj_x  = (const float*)d_in[14];
    const float* bproj_x  = (const float*)d_in[15];
    const float* Wproj_y  = (const float*)d_in[16];
    const float* bproj_y  = (const float*)d_in[17];
    float* out = (float*)d_out;

    static bool init = false;
    static cudaStream_t s1, s2;
    static cudaEvent_t eFork1, eFork2, eWq, eQx, eQy, eVc, eWp, eF, ePy;
    if (!init) {
        init = true;
        cudaStreamCreateWithFlags(&s1, cudaStreamNonBlocking);
        cudaStreamCreateWithFlags(&s2, cudaStreamNonBlocking);
        cudaEventCreateWithFlags(&eFork1, cudaEventDisableTiming);
        cudaEventCreateWithFlags(&eFork2, cudaEventDisableTiming);
        cudaEventCreateWithFlags(&eWq, cudaEventDisableTiming);
        cudaEventCreateWithFlags(&eQx, cudaEventDisableTiming);
        cudaEventCreateWithFlags(&eQy, cudaEventDisableTiming);
        cudaEventCreateWithFlags(&eVc, cudaEventDisableTiming);
        cudaEventCreateWithFlags(&eWp, cudaEventDisableTiming);
        cudaEventCreateWithFlags(&eF,  cudaEventDisableTiming);
        cudaEventCreateWithFlags(&ePy, cudaEventDisableTiming);
        cudaFuncSetAttribute(mma_gemm, cudaFuncAttributeMaxDynamicSharedMemorySize, GSMEM);
        cudaFuncSetAttribute(mma_gemm_wide, cudaFuncAttributeMaxDynamicSharedMemorySize, WSMEM);
        cudaFuncSetAttribute(flash_attn, cudaFuncAttributeMaxDynamicSharedMemorySize, FSMEM);
    }

    float *qkvx, *qkvy;
    bf16 *xmh, *xml, *ymh, *yml, *wqxh, *wqxl, *wqyh, *wqyl, *wpxh, *wpxl, *wpyh, *wpyl;
    bf16 *Qh, *Ql, *Kh, *Kl, *Vth, *Vtl, *Oh, *Ol;
    cudaGetSymbolAddress((void**)&qkvx, g_qkvx);
    cudaGetSymbolAddress((void**)&qkvy, g_qkvy);
    cudaGetSymbolAddress((void**)&xmh,  g_xm_h);  cudaGetSymbolAddress((void**)&xml, g_xm_l);
    cudaGetSymbolAddress((void**)&ymh,  g_ym_h);  cudaGetSymbolAddress((void**)&yml, g_ym_l);
    cudaGetSymbolAddress((void**)&wqxh, g_WqxT_h); cudaGetSymbolAddress((void**)&wqxl, g_WqxT_l);
    cudaGetSymbolAddress((void**)&wqyh, g_WqyT_h); cudaGetSymbolAddress((void**)&wqyl, g_WqyT_l);
    cudaGetSymbolAddress((void**)&wpxh, g_WpxT_h); cudaGetSymbolAddress((void**)&wpxl, g_WpxT_l);
    cudaGetSymbolAddress((void**)&wpyh, g_WpyT_h); cudaGetSymbolAddress((void**)&wpyl, g_WpyT_l);
    cudaGetSymbolAddress((void**)&Qh, g_Qh);   cudaGetSymbolAddress((void**)&Ql, g_Ql);
    cudaGetSymbolAddress((void**)&Kh, g_Kh);   cudaGetSymbolAddress((void**)&Kl, g_Kl);
    cudaGetSymbolAddress((void**)&Vth, g_Vth); cudaGetSymbolAddress((void**)&Vtl, g_Vtl);
    cudaGetSymbolAddress((void**)&Oh, g_Oh);   cudaGetSymbolAddress((void**)&Ol, g_Ol);

    dim3 t328(32, 8);

    // fork side streams from the captured (default) stream
    cudaEventRecord(eFork1, 0);
    cudaStreamWaitEvent(s1, eFork1, 0);
    cudaEventRecord(eFork2, 0);
    cudaStreamWaitEvent(s2, eFork2, 0);

    // main: rms_x
    rms_mod_split<<<NX, 256>>>(x, scale_x, xmh, xml, DX_, 1e-6f);
    // s1: rms_y, wconv_qkv
    rms_mod_split<<<NY, 256, 0, s1>>>(y, scale_y, ymh, yml, DY_, 1e-6f);
    wconv2<<<dim3(QKVN / 32, DX_ / 32, 2), t328, 0, s1>>>(
        Wqkv_x, wqxh, wqxl, DX_, QKVN,
        Wqkv_y, wqyh, wqyl, DY_, QKVN);
    cudaEventRecord(eWq, s1);
    // s2: wconv_proj
    wconv2<<<dim3(DX_ / 32, DX_ / 32, 2), t328, 0, s2>>>(
        Wproj_x, wpxh, wpxl, DX_, DX_,
        Wproj_y, wpyh, wpyl, DX_, DY_);
    cudaEventRecord(eWp, s2);

    // main: qkv_x
    cudaStreamWaitEvent(0, eWq, 0);
    mma_gemm_wide<<<dim3(QKVN / 256, NX / 128), 256, WSMEM>>>(
        xmh, xml, wqxh, wqxl, bqkv_x, qkvx, DX_, DX_, DX_, QKVN);
    cudaEventRecord(eQx, 0);

    // s1: qkv_y
    mma_gemm<<<dim3(QKVN / 128, NY / 128, 1), 256, GSMEM, s1>>>(
        ymh, yml, wqyh, wqyl, bqkv_y, qkvy, nullptr, nullptr,
        DY_, DY_, DY_, QKVN, 0, 0, 0);
    cudaEventRecord(eQy, s1);

    // main: qkv_transform
    cudaStreamWaitEvent(0, eQy, 0);
    qkv_transform<<<(S_ * H_) / 8, 256>>>(rope_cos, rope_sin,
                                          q_norm_x, k_norm_x, q_norm_y, k_norm_y);
    // s1: vconv (concurrent with transform)
    cudaStreamWaitEvent(s1, eQx, 0);
    vconv<<<dim3(S_ / 32, D_ / 32, H_), t328, 0, s1>>>();
    cudaEventRecord(eVc, s1);

    // main: flash
    cudaStreamWaitEvent(0, eVc, 0);
    flash_attn<<<dim3(S_ / 64, H_), 256, FSMEM>>>(Qh, Ql, Kh, Kl, Vth, Vtl, Oh, Ol);
    cudaEventRecord(eF, 0);

    // main: proj_x
    cudaStreamWaitEvent(0, eWp, 0);
    mma_gemm_wide<<<dim3(DX_ / 256, NX / 128), 256, WSMEM>>>(
        Oh, Ol, wpxh, wpxl, bproj_x, out, DX_, DX_, DX_, DX_);

    // s1: proj_y (concurrent with proj_x)
    cudaStreamWaitEvent(s1, eF, 0);
    cudaStreamWaitEvent(s1, eWp, 0);
    mma_gemm<<<dim3(DY_ / 128, NY / 128, 1), 256, GSMEM, s1>>>(
        Oh + (size_t)NX * DX_, Ol + (size_t)NX * DX_, wpyh, wpyl, bproj_y,
        out + (size_t)NX * DX_, nullptr, nullptr,
        DX_, DX_, DX_, DY_, 0, 0, 0);
    cudaEventRecord(ePy, s1);

    // join side streams
    cudaStreamWaitEvent(0, ePy, 0);
}

// round 17
// speedup vs baseline: 1.6173x; 1.0547x over previous
#include <cuda_runtime.h>
#include <cuda_bf16.h>
#include <cuda_fp16.h>
#include <cstdint>
#include <math.h>

#define H_    12
#define D_    128
#define NX    2048
#define NY    256
#define S_    2304
#define DX_   1536
#define DY_   768
#define QKVN  4608

typedef __nv_bfloat16 bf16;

// ---------------- scratch (static device globals; no allocation) ----------------
__device__ __align__(256) float g_qkvx[(size_t)NX * QKVN];
__device__ __align__(256) float g_qkvy[(size_t)NY * QKVN];
__device__ __align__(256) bf16 g_xm_h[(size_t)NX * DX_],  g_xm_l[(size_t)NX * DX_];
__device__ __align__(256) bf16 g_ym_h[(size_t)NY * DY_],  g_ym_l[(size_t)NY * DY_];
__device__ __align__(256) bf16 g_WqxT_h[(size_t)QKVN * DX_], g_WqxT_l[(size_t)QKVN * DX_];
__device__ __align__(256) bf16 g_WqyT_h[(size_t)QKVN * DY_], g_WqyT_l[(size_t)QKVN * DY_];
__device__ __align__(256) bf16 g_WpxT_h[(size_t)DX_ * DX_],  g_WpxT_l[(size_t)DX_ * DX_];
__device__ __align__(256) bf16 g_WpyT_h[(size_t)DY_ * DX_],  g_WpyT_l[(size_t)DY_ * DX_];
__device__ __align__(256) bf16 g_Qh[(size_t)H_ * S_ * D_], g_Ql[(size_t)H_ * S_ * D_];
__device__ __align__(256) bf16 g_Kh[(size_t)H_ * S_ * D_], g_Kl[(size_t)H_ * S_ * D_];
__device__ __align__(256) __half g_Vth[(size_t)H_ * D_ * S_], g_Vtl[(size_t)H_ * D_ * S_];
__device__ __align__(256) bf16 g_Oh[(size_t)S_ * DX_],      g_Ol[(size_t)S_ * DX_];

// ---------------- small helpers ----------------
__device__ __forceinline__ float warp_sum(float v) {
    #pragma unroll
    for (int o = 16; o; o >>= 1) v += __shfl_xor_sync(0xffffffffu, v, o);
    return v;
}
__device__ float block_red(float v, float* sbuf, bool ismax) {
    #pragma unroll
    for (int o = 16; o; o >>= 1)
        v = ismax ? fmaxf(v, __shfl_xor_sync(0xffffffffu, v, o))
                  : v + __shfl_xor_sync(0xffffffffu, v, o);
    int w = threadIdx.x >> 5, nw = blockDim.x >> 5;
    if ((threadIdx.x & 31) == 0) sbuf[w] = v;
    __syncthreads();
    if (threadIdx.x < 32) {
        float t = (threadIdx.x < nw) ? sbuf[threadIdx.x] : (ismax ? -1e30f : 0.f);
        #pragma unroll
        for (int o = 16; o; o >>= 1)
            t = ismax ? fmaxf(t, __shfl_xor_sync(0xffffffffu, t, o))
                      : t + __shfl_xor_sync(0xffffffffu, t, o);
        if (threadIdx.x == 0) sbuf[0] = t;
    }
    __syncthreads();
    float r = sbuf[0];
    __syncthreads();
    return r;
}
__device__ __forceinline__ void split_bf16(float v, bf16& h, bf16& l) {
    h = __float2bfloat16(v);
    l = __float2bfloat16(v - __bfloat162float(h));
}
__device__ __forceinline__ uint32_t pack_hi2(float a, float b, uint32_t& lo) {
    bf16 h0, l0, h1, l1;
    split_bf16(a, h0, l0); split_bf16(b, h1, l1);
    __nv_bfloat162 hp(h0, h1), lp(l0, l1);
    lo = *(uint32_t*)&lp;
    return *(uint32_t*)&hp;
}
__device__ __forceinline__ uint32_t pack2h(float a, float b) {
    __half2 t(__float2half(a), __float2half(b));
    return *(uint32_t*)&t;
}
__device__ __forceinline__ void store4_split(bf16* dh, bf16* dl,
                                             float v0, float v1, float v2, float v3) {
    uint32_t l0, l1;
    uint32_t h0 = pack_hi2(v0, v1, l0);
    uint32_t h1 = pack_hi2(v2, v3, l1);
    *(uint2*)dh = make_uint2(h0, h1);
    *(uint2*)dl = make_uint2(l0, l1);
}
__device__ __forceinline__ uint32_t smem_u32(const void* p) {
    return (uint32_t)__cvta_generic_to_shared(p);
}
__device__ __forceinline__ void cp16(uint32_t s, const void* g) {
    asm volatile("cp.async.cg.shared.global [%0], [%1], 16;" :: "r"(s), "l"(g));
}
__device__ __forceinline__ void ldmx4(uint32_t* r, uint32_t a) {
    asm volatile("ldmatrix.sync.aligned.m8n8.x4.shared.b16 {%0,%1,%2,%3}, [%4];"
                 : "=r"(r[0]), "=r"(r[1]), "=r"(r[2]), "=r"(r[3]) : "r"(a));
}
__device__ __forceinline__ void mma16816(float* c, const uint32_t* a, uint32_t b0, uint32_t b1) {
    asm volatile(
        "mma.sync.aligned.m16n8k16.row.col.f32.bf16.bf16.f32 "
        "{%0,%1,%2,%3}, {%4,%5,%6,%7}, {%8,%9}, {%0,%1,%2,%3};"
        : "+f"(c[0]), "+f"(c[1]), "+f"(c[2]), "+f"(c[3])
        : "r"(a[0]), "r"(a[1]), "r"(a[2]), "r"(a[3]), "r"(b0), "r"(b1));
}
__device__ __forceinline__ void mma16816h(float* c, const uint32_t* a, uint32_t b0, uint32_t b1) {
    asm volatile(
        "mma.sync.aligned.m16n8k16.row.col.f32.f16.f16.f32 "
        "{%0,%1,%2,%3}, {%4,%5,%6,%7}, {%8,%9}, {%0,%1,%2,%3};"
        : "+f"(c[0]), "+f"(c[1]), "+f"(c[2]), "+f"(c[3])
        : "r"(a[0]), "r"(a[1]), "r"(a[2]), "r"(a[3]), "r"(b0), "r"(b1));
}

// ---------------- bf16x3 HMMA GEMM, narrow 128x128 ----------------
#define PADB   80
#define TILEB  (128 * PADB)
#define STAGEB (4 * TILEB)
#define GSMEM  (2 * STAGEB)

__global__ __launch_bounds__(256, 2)
void mma_gemm(const bf16* __restrict__ Ah, const bf16* __restrict__ Al,
              const bf16* __restrict__ Bh, const bf16* __restrict__ Bl,
              const float* __restrict__ bias,
              float* __restrict__ Cf, bf16* __restrict__ Ch, bf16* __restrict__ Cl,
              int K, int lda, int ldb, int ldc,
              long sA, long sB, long sC)
{
    extern __shared__ char smem[];
    uint32_t sb = smem_u32(smem);
    int tid = threadIdx.x, wid = tid >> 5, lane = tid & 31;
    int wr = wid >> 1, wc = wid & 1;

    const bf16* pAh = Ah + (size_t)blockIdx.z * sA + (size_t)blockIdx.y * 128 * lda;
    const bf16* pAl = Al + (size_t)blockIdx.z * sA + (size_t)blockIdx.y * 128 * lda;
    const bf16* pBh = Bh + (size_t)blockIdx.z * sB + (size_t)blockIdx.x * 128 * ldb;
    const bf16* pBl = Bl + (size_t)blockIdx.z * sB + (size_t)blockIdx.x * 128 * ldb;

    const int NC = K >> 5;

    auto load_stage = [&](int st, int k0) {
        uint32_t s0 = sb + st * STAGEB;
        const bf16* srcs[4] = {pAh, pAl, pBh, pBl};
        #pragma unroll
        for (int t = 0; t < 4; t++) {
            int ldt = (t < 2) ? lda : ldb;
            const char* gb = (const char*)srcs[t] + (size_t)k0 * 2;
            #pragma unroll
            for (int i = 0; i < 2; i++) {
                int idx = tid + (i << 8);
                int row = idx >> 2, ch = idx & 3;
                cp16(s0 + t * TILEB + row * PADB + ch * 16,
                     gb + (size_t)row * ldt * 2 + ch * 16);
            }
        }
        asm volatile("cp.async.commit_group;");
    };

    float acc[2][8][4];
    #pragma unroll
    for (int i = 0; i < 2; i++)
        #pragma unroll
        for (int j = 0; j < 8; j++)
            #pragma unroll
            for (int r = 0; r < 4; r++) acc[i][j][r] = 0.f;

    int r8 = lane & 7, seg = lane >> 3;
    int a_row = (seg & 1) * 8 + r8;
    int a_kb  = (seg >> 1) * 16;
    int b_row = (seg >> 1) * 8 + r8;
    int b_kb  = (seg & 1) * 16;

    load_stage(0, 0);

    for (int i = 0; i < NC; i++) {
        asm volatile("cp.async.wait_group 0;");
        __syncthreads();
        if (i + 1 < NC) load_stage((i + 1) & 1, (i + 1) << 5);

        uint32_t base = sb + (i & 1) * STAGEB;
        #pragma unroll
        for (int ks = 0; ks < 2; ks++) {
            int kb = ks * 32;
            uint32_t ah[2][4], al[2][4], bh[4][4], bl[4][4];
            #pragma unroll
            for (int mi = 0; mi < 2; mi++) {
                uint32_t ad = base + (wr * 32 + mi * 16 + a_row) * PADB + kb + a_kb;
                ldmx4(ah[mi], ad);
                ldmx4(al[mi], ad + TILEB);
            }
            #pragma unroll
            for (int nj = 0; nj < 4; nj++) {
                uint32_t bd = base + 2 * TILEB + (wc * 64 + nj * 16 + b_row) * PADB + kb + b_kb;
                ldmx4(bh[nj], bd);
                ldmx4(bl[nj], bd + TILEB);
            }
            #pragma unroll
            for (int mi = 0; mi < 2; mi++)
                #pragma unroll
                for (int nt = 0; nt < 8; nt++) {
                    int nj = nt >> 1, hf = (nt & 1) * 2;
                    mma16816(acc[mi][nt], ah[mi], bh[nj][hf], bh[nj][hf + 1]);
                    mma16816(acc[mi][nt], ah[mi], bl[nj][hf], bl[nj][hf + 1]);
                    mma16816(acc[mi][nt], al[mi], bh[nj][hf], bh[nj][hf + 1]);
                }
        }
    }

    int brow = blockIdx.y * 128 + wr * 32 + (lane >> 2);
    int bcol = blockIdx.x * 128 + wc * 64 + (lane & 3) * 2;
    #pragma unroll
    for (int mi = 0; mi < 2; mi++)
        #pragma unroll
        for (int nt = 0; nt < 8; nt++)
            #pragma unroll
            for (int rh = 0; rh < 2; rh++) {
                int rr = brow + mi * 16 + rh * 8;
                int cc = bcol + nt * 8;
                float v0 = acc[mi][nt][rh * 2 + 0];
                float v1 = acc[mi][nt][rh * 2 + 1];
                if (bias) { v0 += __ldg(bias + cc); v1 += __ldg(bias + cc + 1); }
                size_t ci = (size_t)blockIdx.z * sC + (size_t)rr * ldc + cc;
                if (Cf) *(float2*)(Cf + ci) = make_float2(v0, v1);
                if (Ch) {
                    bf16 h0, l0, h1, l1;
                    split_bf16(v0, h0, l0); split_bf16(v1, h1, l1);
                    *(__nv_bfloat162*)(Ch + ci) = __nv_bfloat162(h0, h1);
                    *(__nv_bfloat162*)(Cl + ci) = __nv_bfloat162(l0, l1);
                }
            }
}

// ---------------- bf16x3 HMMA GEMM, wide 128x256 ----------------
#define WPAD  80
#define WTA   (128 * WPAD)
#define WTB   (256 * WPAD)
#define WSTG  (2 * WTA + 2 * WTB)
#define WSMEM (3 * WSTG)

__global__ __launch_bounds__(256, 1)
void mma_gemm_wide(const bf16* __restrict__ Ah, const bf16* __restrict__ Al,
                   const bf16* __restrict__ Bh, const bf16* __restrict__ Bl,
                   const float* __restrict__ bias, float* __restrict__ Cf,
                   int K, int lda, int ldb, int ldc)
{
    extern __shared__ char smem[];
    uint32_t sb = smem_u32(smem);
    int tid = threadIdx.x, wid = tid >> 5, lane = tid & 31;
    int wr = wid & 1, wc = wid >> 1;

    const bf16* pAh = Ah + (size_t)blockIdx.y * 128 * lda;
    const bf16* pAl = Al + (size_t)blockIdx.y * 128 * lda;
    const bf16* pBh = Bh + (size_t)blockIdx.x * 256 * ldb;
    const bf16* pBl = Bl + (size_t)blockIdx.x * 256 * ldb;

    const int NC = K >> 5;

    auto load_stage = [&](int st, int k0) {
        uint32_t s0 = sb + st * WSTG;
        const char* gah = (const char*)pAh + (size_t)k0 * 2;
        const char* gal = (const char*)pAl + (size_t)k0 * 2;
        #pragma unroll
        for (int i = 0; i < 2; i++) {
            int idx = tid + (i << 8);
            int row = idx >> 2, ch = idx & 3;
            size_t go = (size_t)row * lda * 2 + ch * 16;
            cp16(s0 + row * WPAD + ch * 16,        gah + go);
            cp16(s0 + WTA + row * WPAD + ch * 16,  gal + go);
        }
        const char* gbh = (const char*)pBh + (size_t)k0 * 2;
        const char* gbl = (const char*)pBl + (size_t)k0 * 2;
        #pragma unroll
        for (int i = 0; i < 4; i++) {
            int idx = tid + (i << 8);
            int row = idx >> 2, ch = idx & 3;
            size_t go = (size_t)row * ldb * 2 + ch * 16;
            cp16(s0 + 2 * WTA + row * WPAD + ch * 16,       gbh + go);
            cp16(s0 + 2 * WTA + WTB + row * WPAD + ch * 16, gbl + go);
        }
        asm volatile("cp.async.commit_group;");
    };

    float acc[4][8][4];
    #pragma unroll
    for (int i = 0; i < 4; i++)
        #pragma unroll
        for (int j = 0; j < 8; j++)
            #pragma unroll
            for (int r = 0; r < 4; r++) acc[i][j][r] = 0.f;

    int r8 = lane & 7, seg = lane >> 3;
    int a_row = (seg & 1) * 8 + r8;
    int a_kb  = (seg >> 1) * 16;
    int b_row = (seg >> 1) * 8 + r8;
    int b_kb  = (seg & 1) * 16;

    load_stage(0, 0);
    load_stage(1, 32);

    for (int i = 0; i < NC; i++) {
        if (i < NC - 1) { asm volatile("cp.async.wait_group 1;"); }
        else            { asm volatile("cp.async.wait_group 0;"); }
        __syncthreads();
        if (i + 2 < NC) load_stage((i + 2) % 3, (i + 2) << 5);

        uint32_t base = sb + (i % 3) * WSTG;
        #pragma unroll
        for (int ks = 0; ks < 2; ks++) {
            int kb = ks * 32;
            uint32_t ah[4][4], al[4][4];
            #pragma unroll
            for (int mi = 0; mi < 4; mi++) {
                uint32_t ad = base + (wr * 64 + mi * 16 + a_row) * WPAD + kb + a_kb;
                ldmx4(ah[mi], ad);
                ldmx4(al[mi], ad + WTA);
            }
            #pragma unroll
            for (int nj = 0; nj < 4; nj++) {
                uint32_t bh[4], bl[4];
                uint32_t bd = base + 2 * WTA + (wc * 64 + nj * 16 + b_row) * WPAD + kb + b_kb;
                ldmx4(bh, bd);
                ldmx4(bl, bd + WTB);
                #pragma unroll
                for (int mi = 0; mi < 4; mi++)
                    #pragma unroll
                    for (int half = 0; half < 2; half++) {
                        int nt = nj * 2 + half, hf = half * 2;
                        mma16816(acc[mi][nt], ah[mi], bh[hf], bh[hf + 1]);
                        mma16816(acc[mi][nt], ah[mi], bl[hf], bl[hf + 1]);
                        mma16816(acc[mi][nt], al[mi], bh[hf], bh[hf + 1]);
                    }
            }
        }
    }

    int brow = blockIdx.y * 128 + wr * 64 + (lane >> 2);
    int bcol = blockIdx.x * 256 + wc * 64 + (lane & 3) * 2;
    #pragma unroll
    for (int mi = 0; mi < 4; mi++)
        #pragma unroll
        for (int nt = 0; nt < 8; nt++)
            #pragma unroll
            for (int rh = 0; rh < 2; rh++) {
                int rr = brow + mi * 16 + rh * 8;
                int cc = bcol + nt * 8;
                float v0 = acc[mi][nt][rh * 2 + 0];
                float v1 = acc[mi][nt][rh * 2 + 1];
                if (bias) { v0 += __ldg(bias + cc); v1 += __ldg(bias + cc + 1); }
                *(float2*)(Cf + (size_t)rr * ldc + cc) = make_float2(v0, v1);
            }
}

// ---------------- fused flash attention (r13 structure; PV in fp16 x2) ----------------
#define QPAD  272
#define KPAD  272
#define VPAD  144
#define QTB   (64 * QPAD)
#define KTB   (64 * KPAD)
#define VTB   (128 * VPAD)
#define STGB  (2 * KTB + 2 * VTB)
#define FSMEM (2 * QTB + 2 * STGB)

__global__ __launch_bounds__(256, 1)
void flash_attn(const bf16* __restrict__ Qh_, const bf16* __restrict__ Ql_,
                const bf16* __restrict__ Kh_, const bf16* __restrict__ Kl_,
                const __half* __restrict__ Vh_, const __half* __restrict__ Vl_,
                bf16* __restrict__ Oh_, bf16* __restrict__ Ol_)
{
    extern __shared__ char smem[];
    uint32_t sb = smem_u32(smem);
    int tid = threadIdx.x, wid = tid >> 5, lane = tid & 31;
    int wg = wid >> 2, wid4 = wid & 3, tid4 = tid & 127;
    int h = blockIdx.y;
    int q0 = blockIdx.x * 64;

    const bf16* Qhb = Qh_ + ((size_t)h * S_ + q0) * D_;
    const bf16* Qlb = Ql_ + ((size_t)h * S_ + q0) * D_;
    const bf16* Khb = Kh_ + (size_t)h * S_ * D_;
    const bf16* Klb = Kl_ + (size_t)h * S_ * D_;
    const __half* Vhb = Vh_ + (size_t)h * D_ * S_;
    const __half* Vlb = Vl_ + (size_t)h * D_ * S_;

    const uint32_t Qs = sb, STG0 = sb + 2 * QTB;
    const uint32_t MYB = STG0 + (uint32_t)wg * STGB;

    #pragma unroll
    for (int i = 0; i < 4; i++) {
        int c = tid + (i << 8);
        int row = c >> 4, ch = c & 15;
        cp16(Qs + row * QPAD + ch * 16,        (const char*)Qhb + (size_t)row * 256 + ch * 16);
        cp16(Qs + QTB + row * QPAD + ch * 16,  (const char*)Qlb + (size_t)row * 256 + ch * 16);
    }
    auto load_K = [&](int blk) {
        const char* kh = (const char*)(Khb + (size_t)blk * 64 * D_);
        const char* kl = (const char*)(Klb + (size_t)blk * 64 * D_);
        #pragma unroll
        for (int i = 0; i < 8; i++) {
            int c = tid4 + (i << 7);
            int row = c >> 4, ch = c & 15;
            cp16(MYB + row * KPAD + ch * 16,       kh + (size_t)row * 256 + ch * 16);
            cp16(MYB + KTB + row * KPAD + ch * 16, kl + (size_t)row * 256 + ch * 16);
        }
        asm volatile("cp.async.commit_group;");
    };
    auto load_V = [&](int blk) {
        const char* vh = (const char*)(Vhb + (size_t)blk * 64);
        const char* vl = (const char*)(Vlb + (size_t)blk * 64);
        #pragma unroll
        for (int i = 0; i < 8; i++) {
            int c = tid4 + (i << 7);
            int row = c >> 3, ch = c & 7;
            cp16(MYB + 2 * KTB + row * VPAD + ch * 16,       vh + (size_t)row * S_ * 2 + ch * 16);
            cp16(MYB + 2 * KTB + VTB + row * VPAD + ch * 16, vl + (size_t)row * S_ * 2 + ch * 16);
        }
        asm volatile("cp.async.commit_group;");
    };
    load_K(wg);
    load_V(wg);
    asm volatile("cp.async.wait_group 0;");
    __syncthreads();

    int r8 = lane & 7, seg = lane >> 3;
    int a_row = (seg & 1) * 8 + r8;
    int a_kb  = (seg >> 1) * 16;
    int b_row = (seg >> 1) * 8 + r8;
    int b_kb  = (seg & 1) * 16;

    float o[16][4];
    #pragma unroll
    for (int t = 0; t < 16; t++)
        #pragma unroll
        for (int r = 0; r < 4; r++) o[t][r] = 0.f;
    float m0 = -1e30f, m1 = -1e30f, l0 = 0.f, l1 = 0.f;
    const float sc = 0.08838834764831845f;
    const int bar_id = 1 + wg;

    const int NIT = (S_ / 64) / 2;
    for (int it = 0; it < NIT; it++) {
        uint32_t Ks = MYB;
        uint32_t Vs = MYB + 2 * KTB;
        bool more = (it + 1 < NIT);

        float st[8][4];
        #pragma unroll
        for (int t = 0; t < 8; t++)
            #pragma unroll
            for (int r = 0; r < 4; r++) st[t][r] = 0.f;

        #pragma unroll
        for (int ks = 0; ks < 8; ks++) {
            int kb = ks * 32;
            uint32_t qh[4], ql[4], kh[4][4], kl[4][4];
            uint32_t qa = Qs + (wid4 * 16 + a_row) * QPAD + kb + a_kb;
            ldmx4(qh, qa);
            ldmx4(ql, qa + QTB);
            #pragma unroll
            for (int nj = 0; nj < 4; nj++) {
                uint32_t ka = Ks + (nj * 16 + b_row) * KPAD + kb + b_kb;
                ldmx4(kh[nj], ka);
                ldmx4(kl[nj], ka + KTB);
            }
            #pragma unroll
            for (int nt = 0; nt < 8; nt++) {
                int nj = nt >> 1, hf = (nt & 1) * 2;
                mma16816(st[nt], qh, kh[nj][hf], kh[nj][hf + 1]);
                mma16816(st[nt], qh, kl[nj][hf], kl[nj][hf + 1]);
                mma16816(st[nt], ql, kh[nj][hf], kh[nj][hf + 1]);
            }
        }

        asm volatile("bar.sync %0, 128;" :: "r"(bar_id) : "memory");
        if (more) load_K(wg + 2 * (it + 1));

        float bm0 = -1e30f, bm1 = -1e30f;
        #pragma unroll
        for (int t = 0; t < 8; t++) {
            bm0 = fmaxf(bm0, fmaxf(st[t][0], st[t][1]));
            bm1 = fmaxf(bm1, fmaxf(st[t][2], st[t][3]));
        }
        #pragma unroll
        for (int off = 1; off <= 2; off <<= 1) {
            bm0 = fmaxf(bm0, __shfl_xor_sync(0xffffffffu, bm0, off));
            bm1 = fmaxf(bm1, __shfl_xor_sync(0xffffffffu, bm1, off));
        }
        float nm0 = fmaxf(m0, bm0), nm1 = fmaxf(m1, bm1);
        float al0 = __expf((m0 - nm0) * sc), al1 = __expf((m1 - nm1) * sc);
        float ps0 = 0.f, ps1 = 0.f;
        #pragma unroll
        for (int t = 0; t < 8; t++) {
            st[t][0] = __expf((st[t][0] - nm0) * sc);
            st[t][1] = __expf((st[t][1] - nm0) * sc);
            st[t][2] = __expf((st[t][2] - nm1) * sc);
            st[t][3] = __expf((st[t][3] - nm1) * sc);
            ps0 += st[t][0] + st[t][1];
            ps1 += st[t][2] + st[t][3];
        }
        #pragma unroll
        for (int off = 1; off <= 2; off <<= 1) {
            ps0 += __shfl_xor_sync(0xffffffffu, ps0, off);
            ps1 += __shfl_xor_sync(0xffffffffu, ps1, off);
        }
        l0 = l0 * al0 + ps0;
        l1 = l1 * al1 + ps1;
        m0 = nm0; m1 = nm1;
        #pragma unroll
        for (int t = 0; t < 16; t++) {
            o[t][0] *= al0; o[t][1] *= al0;
            o[t][2] *= al1; o[t][3] *= al1;
        }

        // ---- O += P V : P single fp16 (10-bit mantissa), V fp16 hi+lo -> 2 MMAs ----
        #pragma unroll
        for (int g = 0; g < 4; g++) {
            uint32_t aph[4];
            #pragma unroll
            for (int half = 0; half < 2; half++) {
                float* s0 = st[2 * g + half];
                aph[2 * half + 0] = pack2h(s0[0], s0[1]);
                aph[2 * half + 1] = pack2h(s0[2], s0[3]);
            }
            #pragma unroll
            for (int nj = 0; nj < 8; nj++) {
                uint32_t vh[4], vl[4];
                uint32_t va = Vs + (nj * 16 + b_row) * VPAD + g * 32 + b_kb;
                ldmx4(vh, va);
                ldmx4(vl, va + VTB);
                #pragma unroll
                for (int half = 0; half < 2; half++) {
                    int t = nj * 2 + half;
                    int hf = half * 2;
                    mma16816h(o[t], aph, vh[hf], vh[hf + 1]);
                    mma16816h(o[t], aph, vl[hf], vl[hf + 1]);
                }
            }
        }

        asm volatile("bar.sync %0, 128;" :: "r"(bar_id) : "memory");
        if (more) {
            load_V(wg + 2 * (it + 1));
            asm volatile("cp.async.wait_group 0;");
            asm volatile("bar.sync %0, 128;" :: "r"(bar_id) : "memory");
        }
    }

    float* sf = (float*)smem;
    __syncthreads();
    if (wg == 1) {
        float* dml = sf + tid4 * 4;
        dml[0] = m0; dml[1] = m1; dml[2] = l0; dml[3] = l1;
        float* doo = sf + 512 + tid4 * 64;
        #pragma unroll
        for (int t = 0; t < 16; t++)
            *(float4*)(doo + t * 4) = make_float4(o[t][0], o[t][1], o[t][2], o[t][3]);
    }
    __syncthreads();
    if (wg == 0) {
        float* pml = sf + tid4 * 4;
        float pm0 = pml[0], pm1 = pml[1], pl0 = pml[2], pl1 = pml[3];
        float* poo = sf + 512 + tid4 * 64;
        float M0 = fmaxf(m0, pm0), M1 = fmaxf(m1, pm1);
        float w00 = __expf((m0 - M0) * sc), w01 = __expf((pm0 - M0) * sc);
        float w10 = __expf((m1 - M1) * sc), w11 = __expf((pm1 - M1) * sc);
        float L0 = l0 * w00 + pl0 * w01;
        float L1 = l1 * w10 + pl1 * w11;
        float i0 = 1.f / L0, i1 = 1.f / L1;
        int sr0 = q0 + wid4 * 16 + (lane >> 2);
        #pragma unroll
        for (int t = 0; t < 16; t++) {
            float4 po = *(float4*)(poo + t * 4);
            float v0 = (o[t][0] * w00 + po.x * w01) * i0;
            float v1 = (o[t][1] * w00 + po.y * w01) * i0;
            float v2 = (o[t][2] * w10 + po.z * w11) * i1;
            float v3 = (o[t][3] * w10 + po.w * w11) * i1;
            int cc = h * 128 + t * 8 + (lane & 3) * 2;
            bf16 h0, lo0, h1, lo1;
            split_bf16(v0, h0, lo0); split_bf16(v1, h1, lo1);
            size_t ci = (size_t)sr0 * DX_ + cc;
            *(__nv_bfloat162*)(Oh_ + ci) = __nv_bfloat162(h0, h1);
            *(__nv_bfloat162*)(Ol_ + ci) = __nv_bfloat162(lo0, lo1);
            split_bf16(v2, h0, lo0); split_bf16(v3, h1, lo1);
            ci = (size_t)(sr0 + 8) * DX_ + cc;
            *(__nv_bfloat162*)(Oh_ + ci) = __nv_bfloat162(h0, h1);
            *(__nv_bfloat162*)(Ol_ + ci) = __nv_bfloat162(lo0, lo1);
        }
    }
}

// ---------------- RMSNorm + modulation, split hi/lo ----------------
__global__ void rms_mod_split(const float* __restrict__ X, const float* __restrict__ sc,
                              bf16* __restrict__ oh, bf16* __restrict__ ol, int Dm, float eps) {
    __shared__ float sbuf[32];
    size_t row = blockIdx.x;
    const float* xr = X + row * Dm;
    float ss = 0.f;
    for (int i = threadIdx.x; i < Dm; i += blockDim.x) { float t = xr[i]; ss += t * t; }
    ss = block_red(ss, sbuf, false);
    float r = rsqrtf(ss / (float)Dm + eps);
    for (int i = threadIdx.x; i < Dm; i += blockDim.x) {
        float v = xr[i] * r * (1.f + sc[i]);
        bf16 h, l; split_bf16(v, h, l);
        oh[row * Dm + i] = h; ol[row * Dm + i] = l;
    }
}

// ---------------- dual weight transpose + split ----------------
__global__ void wconv2(const float* __restrict__ W0, bf16* __restrict__ Th0, bf16* __restrict__ Tl0,
                       int K0, int N0,
                       const float* __restrict__ W1, bf16* __restrict__ Th1, bf16* __restrict__ Tl1,
                       int K1, int N1) {
    const float* W; bf16 *Th, *Tl; int K, N;
    if (blockIdx.z == 0) { W = W0; Th = Th0; Tl = Tl0; K = K0; N = N0; }
    else                 { W = W1; Th = Th1; Tl = Tl1; K = K1; N = N1; }
    int n0 = blockIdx.x * 32, k0 = blockIdx.y * 32;
    if (n0 >= N || k0 >= K) return;
    __shared__ float t[32][33];
    int tx = threadIdx.x, ty = threadIdx.y;
    #pragma unroll
    for (int j = 0; j < 32; j += 8)
        t[ty + j][tx] = W[(size_t)(k0 + ty + j) * N + n0 + tx];
    __syncthreads();
    #pragma unroll
    for (int j = 0; j < 32; j += 8) {
        float v = t[tx][ty + j];
        size_t o = (size_t)(n0 + ty + j) * K + k0 + tx;
        bf16 h, l; split_bf16(v, h, l);
        Th[o] = h; Tl[o] = l;
    }
}

// ---------------- Q/K per-head RMSNorm + RoPE (warp per (s,h)) ----------------
__global__ __launch_bounds__(256)
void qkv_transform(const float* __restrict__ rope_cos, const float* __restrict__ rope_sin,
                   const float* __restrict__ qnx, const float* __restrict__ knx,
                   const float* __restrict__ qny, const float* __restrict__ kny) {
    int gw = blockIdx.x * 8 + (threadIdx.x >> 5);
    int lane = threadIdx.x & 31;
    int s = gw / H_, h = gw - s * H_;
    bool isx = (s < NX);
    const float* base = isx ? (g_qkvx + (size_t)s * QKVN) : (g_qkvy + (size_t)(s - NX) * QKVN);
    int d0 = lane * 4;
    int col = h * D_ + d0;

    float4 q = *(const float4*)(base + col);
    float4 k = *(const float4*)(base + DX_ + col);

    float sq = warp_sum(q.x * q.x + q.y * q.y + q.z * q.z + q.w * q.w);
    float sk = warp_sum(k.x * k.x + k.y * k.y + k.z * k.z + k.w * k.w);
    float rq = rsqrtf(sq * (1.f / D_) + 1e-5f);
    float rk = rsqrtf(sk * (1.f / D_) + 1e-5f);

    float4 wq = isx ? *(const float4*)(qnx + d0) : *(const float4*)(qny + d0);
    float4 wk = isx ? *(const float4*)(knx + d0) : *(const float4*)(kny + d0);
    float q0 = q.x * rq * wq.x, q1 = q.y * rq * wq.y, q2 = q.z * rq * wq.z, q3 = q.w * rq * wq.w;
    float k0 = k.x * rk * wk.x, k1 = k.y * rk * wk.y, k2 = k.z * rk * wk.z, k3 = k.w * rk * wk.w;

    if (isx) {
        size_t rbase = ((size_t)s * H_ + h) * (D_ / 2) + (d0 >> 1);
        float2 c = *(const float2*)(rope_cos + rbase);
        float2 sn = *(const float2*)(rope_sin + rbase);
        float e, o_;
        e = q0 * c.x - q1 * sn.x;  o_ = q0 * sn.x + q1 * c.x;  q0 = e; q1 = o_;
        e = q2 * c.y - q3 * sn.y;  o_ = q2 * sn.y + q3 * c.y;  q2 = e; q3 = o_;
        e = k0 * c.x - k1 * sn.x;  o_ = k0 * sn.x + k1 * c.x;  k0 = e; k1 = o_;
        e = k2 * c.y - k3 * sn.y;  o_ = k2 * sn.y + k3 * c.y;  k2 = e; k3 = o_;
    }
    size_t o = ((size_t)h * S_ + s) * D_ + d0;
    store4_split(g_Qh + o, g_Ql + o, q0, q1, q2, q3);
    store4_split(g_Kh + o, g_Kl + o, k0, k1, k2, k3);
}

// ---------------- V transpose to [H][D][S], split fp16 hi/lo ----------------
__global__ void vconv() {
    __shared__ float t[32][33];
    int s0 = blockIdx.x * 32, d0 = blockIdx.y * 32, h = blockIdx.z;
    int tx = threadIdx.x, ty = threadIdx.y;
    #pragma unroll
    for (int j = 0; j < 32; j += 8) {
        int s = s0 + ty + j;
        const float* base = (s < NX) ? (g_qkvx + (size_t)s * QKVN)
                                     : (g_qkvy + (size_t)(s - NX) * QKVN);
        t[ty + j][tx] = base[2 * DX_ + h * D_ + d0 + tx];
    }
    __syncthreads();
    #pragma unroll
    for (int j = 0; j < 32; j += 8) {
        float v = t[tx][ty + j];
        size_t o = ((size_t)h * D_ + d0 + ty + j) * S_ + s0 + tx;
        __half hh = __float2half(v);
        __half ll = __float2half(v - __half2float(hh));
        g_Vth[o] = hh; g_Vtl[o] = ll;
    }
}

// ---------------- launch (stream-parallel graph) ----------------
extern "C" void kernel_launch(void* const* d_in, const int* in_sizes, int n_in,
                              void* d_out, int out_size)
{
    const float* x        = (const float*)d_in[0];
    const float* y        = (const float*)d_in[1];
    const float* scale_x  = (const float*)d_in[2];
    const float* scale_y  = (const float*)d_in[3];
    const float* rope_cos = (const float*)d_in[4];
    const float* rope_sin = (const float*)d_in[5];
    const float* Wqkv_x   = (const float*)d_in[6];
    const float* bqkv_x   = (const float*)d_in[7];
    const float* Wqkv_y   = (const float*)d_in[8];
    const float* bqkv_y   = (const float*)d_in[9];
    const float* q_norm_x = (const float*)d_in[10];
    const float* k_norm_x = (const float*)d_in[11];
    const float* q_norm_y = (const float*)d_in[12];
    const float* k_norm_y = (const float*)d_in[13];
    const float* Wproj_x  = (const float*)d_in[14];
    const float* bproj_x  = (const float*)d_in[15];
    const float* Wproj_y  = (const float*)d_in[16];
    const float* bproj_y  = (const float*)d_in[17];
    float* out = (float*)d_out;

    static bool init = false;
    static cudaStream_t s1, s2;
    static cudaEvent_t eFork1, eFork2, eWq, eQx, eQy, eVc, eWp, eF, ePy;
    if (!init) {
        init = true;
        cudaStreamCreateWithFlags(&s1, cudaStreamNonBlocking);
        cudaStreamCreateWithFlags(&s2, cudaStreamNonBlocking);
        cudaEventCreateWithFlags(&eFork1, cudaEventDisableTiming);
        cudaEventCreateWithFlags(&eFork2, cudaEventDisableTiming);
        cudaEventCreateWithFlags(&eWq, cudaEventDisableTiming);
        cudaEventCreateWithFlags(&eQx, cudaEventDisableTiming);
        cudaEventCreateWithFlags(&eQy, cudaEventDisableTiming);
        cudaEventCreateWithFlags(&eVc, cudaEventDisableTiming);
        cudaEventCreateWithFlags(&eWp, cudaEventDisableTiming);
        cudaEventCreateWithFlags(&eF,  cudaEventDisableTiming);
        cudaEventCreateWithFlags(&ePy, cudaEventDisableTiming);
        cudaFuncSetAttribute(mma_gemm, cudaFuncAttributeMaxDynamicSharedMemorySize, GSMEM);
        cudaFuncSetAttribute(mma_gemm_wide, cudaFuncAttributeMaxDynamicSharedMemorySize, WSMEM);
        cudaFuncSetAttribute(flash_attn, cudaFuncAttributeMaxDynamicSharedMemorySize, FSMEM);
    }

    float *qkvx, *qkvy;
    bf16 *xmh, *xml, *ymh, *yml, *wqxh, *wqxl, *wqyh, *wqyl, *wpxh, *wpxl, *wpyh, *wpyl;
    bf16 *Qh, *Ql, *Kh, *Kl, *Oh, *Ol;
    __half *Vth, *Vtl;
    cudaGetSymbolAddress((void**)&qkvx, g_qkvx);
    cudaGetSymbolAddress((void**)&qkvy, g_qkvy);
    cudaGetSymbolAddress((void**)&xmh,  g_xm_h);  cudaGetSymbolAddress((void**)&xml, g_xm_l);
    cudaGetSymbolAddress((void**)&ymh,  g_ym_h);  cudaGetSymbolAddress((void**)&yml, g_ym_l);
    cudaGetSymbolAddress((void**)&wqxh, g_WqxT_h); cudaGetSymbolAddress((void**)&wqxl, g_WqxT_l);
    cudaGetSymbolAddress((void**)&wqyh, g_WqyT_h); cudaGetSymbolAddress((void**)&wqyl, g_WqyT_l);
    cudaGetSymbolAddress((void**)&wpxh, g_WpxT_h); cudaGetSymbolAddress((void**)&wpxl, g_WpxT_l);
    cudaGetSymbolAddress((void**)&wpyh, g_WpyT_h); cudaGetSymbolAddress((void**)&wpyl, g_WpyT_l);
    cudaGetSymbolAddress((void**)&Qh, g_Qh);   cudaGetSymbolAddress((void**)&Ql, g_Ql);
    cudaGetSymbolAddress((void**)&Kh, g_Kh);   cudaGetSymbolAddress((void**)&Kl, g_Kl);
    cudaGetSymbolAddress((void**)&Vth, g_Vth); cudaGetSymbolAddress((void**)&Vtl, g_Vtl);
    cudaGetSymbolAddress((void**)&Oh, g_Oh);   cudaGetSymbolAddress((void**)&Ol, g_Ol);

    dim3 t328(32, 8);

    // fork side streams from the captured (default) stream
    cudaEventRecord(eFork1, 0);
    cudaStreamWaitEvent(s1, eFork1, 0);
    cudaEventRecord(eFork2, 0);
    cudaStreamWaitEvent(s2, eFork2, 0);

    // main: rms_x
    rms_mod_split<<<NX, 256>>>(x, scale_x, xmh, xml, DX_, 1e-6f);
    // s1: rms_y, wconv_qkv
    rms_mod_split<<<NY, 256, 0, s1>>>(y, scale_y, ymh, yml, DY_, 1e-6f);
    wconv2<<<dim3(QKVN / 32, DX_ / 32, 2), t328, 0, s1>>>(
        Wqkv_x, wqxh, wqxl, DX_, QKVN,
        Wqkv_y, wqyh, wqyl, DY_, QKVN);
    cudaEventRecord(eWq, s1);
    // s2: wconv_proj
    wconv2<<<dim3(DX_ / 32, DX_ / 32, 2), t328, 0, s2>>>(
        Wproj_x, wpxh, wpxl, DX_, DX_,
        Wproj_y, wpyh, wpyl, DX_, DY_);
    cudaEventRecord(eWp, s2);

    // main: qkv_x
    cudaStreamWaitEvent(0, eWq, 0);
    mma_gemm_wide<<<dim3(QKVN / 256, NX / 128), 256, WSMEM>>>(
        xmh, xml, wqxh, wqxl, bqkv_x, qkvx, DX_, DX_, DX_, QKVN);
    cudaEventRecord(eQx, 0);

    // s1: qkv_y
    mma_gemm<<<dim3(QKVN / 128, NY / 128, 1), 256, GSMEM, s1>>>(
        ymh, yml, wqyh, wqyl, bqkv_y, qkvy, nullptr, nullptr,
        DY_, DY_, DY_, QKVN, 0, 0, 0);
    cudaEventRecord(eQy, s1);

    // main: qkv_transform
    cudaStreamWaitEvent(0, eQy, 0);
    qkv_transform<<<(S_ * H_) / 8, 256>>>(rope_cos, rope_sin,
                                          q_norm_x, k_norm_x, q_norm_y, k_norm_y);
    // s1: vconv (concurrent with transform)
    cudaStreamWaitEvent(s1, eQx, 0);
    vconv<<<dim3(S_ / 32, D_ / 32, H_), t328, 0, s1>>>();
    cudaEventRecord(eVc, s1);

    // main: flash
    cudaStreamWaitEvent(0, eVc, 0);
    flash_attn<<<dim3(S_ / 64, H_), 256, FSMEM>>>(Qh, Ql, Kh, Kl, Vth, Vtl, Oh, Ol);
    cudaEventRecord(eF, 0);

    // main: proj_x
    cudaStreamWaitEvent(0, eWp, 0);
    mma_gemm_wide<<<dim3(DX_ / 256, NX / 128), 256, WSMEM>>>(
        Oh, Ol, wpxh, wpxl, bproj_x, out, DX_, DX_, DX_, DX_);

    // s1: proj_y (concurrent with proj_x)
    cudaStreamWaitEvent(s1, eF, 0);
    cudaStreamWaitEvent(s1, eWp, 0);
    mma_gemm<<<dim3(DY_ / 128, NY / 128, 1), 256, GSMEM, s1>>>(
        Oh + (size_t)NX * DX_, Ol + (size_t)NX * DX_, wpyh, wpyl, bproj_y,
        out + (size_t)NX * DX_, nullptr, nullptr,
        DX_, DX_, DX_, DY_, 0, 0, 0);
    cudaEventRecord(ePy, s1);

    // join side streams
    cudaStreamWaitEvent(0, ePy, 0);
}